// round 11
// baseline (speedup 1.0000x reference)
#include <cuda_runtime.h>
#include <cuda_bf16.h>
#include <cuda_fp16.h>
#include <cstdint>
#include <math.h>

// Problem constants
#define BB 2
#define SS 2048
#define DD 2048
#define HH 16
#define HD 128
#define MM (BB*SS)   // 4096

// ---------------------------------------------------------------------------
// Scratch (static device arrays)
// ---------------------------------------------------------------------------
__device__ __half g_xh[(size_t)MM*DD];                 // fp16-rounded x
__device__ __half g_cth[(size_t)MM*DD];                // fp16-rounded ctx
__device__ __half g_wh[4][(size_t)DD*DD];              // weights^T hi (fp16)
__device__ __half g_wl[4][(size_t)DD*DD];              // weights^T lo (fp16)
// Attention operands, layout [b*H+h][s][d]
__device__ __half g_q16[(size_t)BB*HH*SS*HD];          // Q fp16 (rounded)
__device__ __half g_k16h[(size_t)BB*HH*SS*HD];         // K fp16 hi (exact split)
__device__ __half g_k16l[(size_t)BB*HH*SS*HD];         // K fp16 lo
__device__ __half g_v16[(size_t)BB*HH*SS*HD];          // V fp16 (rounded)

// ---------------------------------------------------------------------------
// PTX helpers — baseline (sm_80+) instructions only (compute_103-safe)
// ---------------------------------------------------------------------------
__device__ __forceinline__ uint32_t smem_u32(const void* p) {
    uint32_t a;
    asm("{ .reg .u64 t; cvta.to.shared.u64 t, %1; cvt.u32.u64 %0, t; }" : "=r"(a) : "l"(p));
    return a;
}
#define CP_ASYNC16(dst, src) \
    asm volatile("cp.async.cg.shared.global [%0], [%1], 16;" :: "r"(dst), "l"(src))
#define CP_COMMIT() asm volatile("cp.async.commit_group;" ::: "memory")
#define CP_WAIT0()  asm volatile("cp.async.wait_group 0;" ::: "memory")

__device__ __forceinline__ void ldsm4(uint32_t* r, uint32_t a) {
    asm volatile("ldmatrix.sync.aligned.m8n8.x4.shared.b16 {%0,%1,%2,%3}, [%4];"
        : "=r"(r[0]), "=r"(r[1]), "=r"(r[2]), "=r"(r[3]) : "r"(a));
}
__device__ __forceinline__ void ldsm4t(uint32_t* r, uint32_t a) {
    asm volatile("ldmatrix.sync.aligned.m8n8.x4.trans.shared.b16 {%0,%1,%2,%3}, [%4];"
        : "=r"(r[0]), "=r"(r[1]), "=r"(r[2]), "=r"(r[3]) : "r"(a));
}
// fp16 MMA (all tensor work)
__device__ __forceinline__ void mma16816h(float* d, const uint32_t* a,
                                          uint32_t b0, uint32_t b1) {
    asm volatile(
        "mma.sync.aligned.m16n8k16.row.col.f32.f16.f16.f32 "
        "{%0,%1,%2,%3}, {%4,%5,%6,%7}, {%8,%9}, {%0,%1,%2,%3};"
        : "+f"(d[0]), "+f"(d[1]), "+f"(d[2]), "+f"(d[3])
        : "r"(a[0]), "r"(a[1]), "r"(a[2]), "r"(a[3]), "r"(b0), "r"(b1));
}
__device__ __forceinline__ float ex2(float x) {
    float r; asm("ex2.approx.f32 %0, %1;" : "=f"(r) : "f"(x)); return r;
}
// split two fp32 into packed fp16x2 hi and lo-residual
__device__ __forceinline__ void split2h(float v0, float v1, uint32_t& H, uint32_t& L) {
    __half h0 = __float2half_rn(v0), h1 = __float2half_rn(v1);
    float r0 = v0 - __half2float(h0), r1 = v1 - __half2float(h1);
    __half2 hh = __halves2half2(h0, h1);
    __half2 ll = __floats2half2_rn(r0, r1);
    H = *(uint32_t*)&hh;
    L = *(uint32_t*)&ll;
}
__device__ __forceinline__ uint32_t pack2h(float v0, float v1) {
    __half2 h = __floats2half2_rn(v0, v1);
    return *(uint32_t*)&h;
}

// ---------------------------------------------------------------------------
// fp32 -> fp16 round (elementwise, layout preserved)
// ---------------------------------------------------------------------------
__global__ void __launch_bounds__(256) round_fp16(const float* __restrict__ src,
                                                  __half* __restrict__ dst)
{
    size_t i = (size_t)blockIdx.x * blockDim.x + threadIdx.x;   // per float4
    float4 v = ((const float4*)src)[i];
    ((__half2*)dst)[2*i]   = __floats2half2_rn(v.x, v.y);
    ((__half2*)dst)[2*i+1] = __floats2half2_rn(v.z, v.w);
}

// ---------------------------------------------------------------------------
// Weight transpose + fp16 hi/lo split: W[K,N] fp32 -> Wt hi/lo [N,K] fp16
// ---------------------------------------------------------------------------
__global__ void __launch_bounds__(256) wtrans_split(const float* __restrict__ W0,
                                                    const float* __restrict__ W1,
                                                    const float* __restrict__ W2,
                                                    const float* __restrict__ W3)
{
    int z = blockIdx.z;
    const float* W = (z == 0) ? W0 : (z == 1) ? W1 : (z == 2) ? W2 : W3;
    __half* Th = g_wh[z];
    __half* Tl = g_wl[z];
    __shared__ float t[32][33];
    int tx = threadIdx.x, ty = threadIdx.y;
    int x  = blockIdx.x * 32 + tx;
    int y0 = blockIdx.y * 32;
#pragma unroll
    for (int r = 0; r < 4; r++)
        t[ty + r*8][tx] = W[(size_t)(y0 + ty + r*8) * DD + x];
    __syncthreads();
    int xo  = y0 + tx;
    int yo0 = blockIdx.x * 32;
#pragma unroll
    for (int r = 0; r < 4; r++) {
        float v = t[tx][ty + r*8];
        __half h = __float2half_rn(v);
        float res = v - __half2float(h);
        size_t o = (size_t)(yo0 + ty + r*8) * DD + xo;
        Th[o] = h;
        Tl[o] = __float2half_rn(res);
    }
}

// ---------------------------------------------------------------------------
// HMMA fp16 2-product GEMM: C[M,N] = A[M,K] @ Wt^T (Wt stored [N,K])
//   A = fp16-rounded activations; W split exactly: C = A*Wh + A*Wl
// Tile 128x128, KC=32, 2-stage cp.async, 8 warps x (32x64), 2 CTA/SM.
// MMA ORDER: full hi-pass then full lo-pass -> acc reuse distance 8 MMAs.
// ---------------------------------------------------------------------------
#define KC 32
#define NCH (DD / KC)          // 64
#define ROWB 80                // smem bytes per row (64B data + 16B pad)
#define TILE_B (128 * ROWB)    // 10240
#define STAGE_B (3 * TILE_B)   // 30720 (A, Wh, Wl)
#define GEMM_SMEM (2 * STAGE_B)

__global__ void __launch_bounds__(256, 2) gemm_tc(const __half* __restrict__ A,
                                                  float* __restrict__ out1,
                                                  const float* __restrict__ bias,
                                                  int mode)
{
    extern __shared__ char smc[];
    const uint32_t sb = smem_u32(smc);
    const int tid  = threadIdx.x;
    const int wid  = tid >> 5;
    const int lane = tid & 31;
    const int z    = blockIdx.z;
    const __half* Bh = g_wh[(mode == 0) ? z : 3];
    const __half* Bl = g_wl[(mode == 0) ? z : 3];
    const int row0 = blockIdx.y * 128;
    const int col0 = blockIdx.x * 128;
    const int mw   = (wid & 3) * 32;      // warp M offset in tile
    const int nw   = (wid >> 2) * 64;     // warp N offset in tile

    float acc[2][8][4];
#pragma unroll
    for (int i = 0; i < 2; i++)
#pragma unroll
        for (int j = 0; j < 8; j++)
#pragma unroll
            for (int q = 0; q < 4; q++) acc[i][j][q] = 0.f;

    auto load_stage = [&](int stage, int c) {
        const int k0 = c * KC;
        const uint32_t base = sb + stage * STAGE_B;
#pragma unroll
        for (int j = 0; j < 6; j++) {
            int i    = tid + j * 256;
            int tile = i >> 9;            // uniform per j
            int r    = (i >> 2) & 127;
            int ch   = i & 3;
            const __half* g;
            if      (tile == 0) g = A  + (size_t)(row0 + r) * DD + k0 + ch * 8;
            else if (tile == 1) g = Bh + (size_t)(col0 + r) * DD + k0 + ch * 8;
            else                g = Bl + (size_t)(col0 + r) * DD + k0 + ch * 8;
            CP_ASYNC16(base + tile * TILE_B + r * ROWB + ch * 16, g);
        }
    };

    load_stage(0, 0);
    CP_COMMIT();

    for (int c = 0; c < NCH; c++) {
        CP_WAIT0();
        __syncthreads();
        if (c + 1 < NCH) load_stage((c + 1) & 1, c + 1);
        CP_COMMIT();
        const uint32_t st = sb + (c & 1) * STAGE_B;

#pragma unroll
        for (int k16 = 0; k16 < 2; k16++) {
            const uint32_t koff = k16 * 32 + (lane >> 4) * 16;
            uint32_t af[2][4];
#pragma unroll
            for (int mm = 0; mm < 2; mm++) {
                const uint32_t ra = (mw + mm * 16 + (lane & 15)) * ROWB + koff;
                ldsm4(af[mm], st + ra);
            }
#pragma unroll
            for (int half = 0; half < 2; half++) {
                uint32_t bfh[2][4], bfl[2][4];
#pragma unroll
                for (int g2 = 0; g2 < 2; g2++) {
                    const int ng = half * 2 + g2;
                    const uint32_t rb = (nw + ng * 16 + (lane & 15)) * ROWB + koff;
                    ldsm4(bfh[g2], st + TILE_B + rb);
                    ldsm4(bfl[g2], st + 2 * TILE_B + rb);
                }
                // hi pass (8 MMAs, all distinct accs), then lo pass:
                // acc reuse distance = 8 MMAs (was 2) -> RAW latency hidden
#pragma unroll
                for (int prod = 0; prod < 2; prod++) {
                    const uint32_t (*bf)[4] = prod ? bfl : bfh;
#pragma unroll
                    for (int mm = 0; mm < 2; mm++)
#pragma unroll
                        for (int g2 = 0; g2 < 2; g2++) {
                            const int ng = half * 2 + g2;
                            mma16816h(acc[mm][ng * 2],     af[mm], bf[g2][0], bf[g2][2]);
                            mma16816h(acc[mm][ng * 2 + 1], af[mm], bf[g2][1], bf[g2][3]);
                        }
                }
            }
        }
    }

    // ---- epilogue
#pragma unroll
    for (int mm = 0; mm < 2; mm++) {
        const int m0 = row0 + mw + mm * 16 + (lane >> 2);
#pragma unroll
        for (int ng = 0; ng < 4; ng++)
#pragma unroll
            for (int hf = 0; hf < 2; hf++) {
                const int n = col0 + nw + ng * 16 + hf * 8 + 2 * (lane & 3);
                const float* d = acc[mm][ng * 2 + hf];
                if (mode == 0) {
                    const int h = n >> 7;
#pragma unroll
                    for (int rr = 0; rr < 2; rr++) {
                        const int m = m0 + rr * 8;
                        const int b = m >> 11, s = m & 2047;
                        size_t off = ((size_t)(b * HH + h) * SS + s) * HD + (n & 127);
                        if (z == 0) {
                            *(uint32_t*)(g_q16 + off) = pack2h(d[rr*2], d[rr*2+1]);
                        } else if (z == 1) {
                            uint32_t Hh, Ll;
                            split2h(d[rr*2], d[rr*2+1], Hh, Ll);
                            *(uint32_t*)(g_k16h + off) = Hh;
                            *(uint32_t*)(g_k16l + off) = Ll;
                        } else {
                            *(uint32_t*)(g_v16 + off) = pack2h(d[rr*2], d[rr*2+1]);
                        }
                    }
                } else {
                    const float b0 = bias[n], b1 = bias[n + 1];
#pragma unroll
                    for (int rr = 0; rr < 2; rr++) {
                        const int m = m0 + rr * 8;
                        *(float2*)(out1 + (size_t)m * DD + n) =
                            make_float2(d[rr * 2] + b0, d[rr * 2 + 1] + b1);
                    }
                }
            }
    }
}

// ---------------------------------------------------------------------------
// Tensor-core flash attention (causal), fp16:
//   S   = Q(fp16) * (Kh + Kl)   -- 2 products, K exact
//   ctx = P(fp16) * V(fp16)     -- 1 product
// QK MMA order: load all 4 n-group fragments, hi pass then lo pass
// (acc reuse distance 8). Per-warp causal tile skip.
// ---------------------------------------------------------------------------
#define KT2 64
#define SROW 272
#define TILEKV (KT2 * SROW)
#define STGKV (3 * TILEKV)             // Kh, Kl, V
#define ATTN_SMEM (2 * STGKV)          // 104448
#define KEXP 0.12751744f               // 1/sqrt(128) * log2(e)

__global__ void __launch_bounds__(256, 1) attn_tc()
{
    extern __shared__ char smc[];
    const uint32_t sb = smem_u32(smc);
    const int tid = threadIdx.x, wid = tid >> 5, lane = tid & 31;
    const int qt   = (SS / 128 - 1) - blockIdx.x;    // longest CTAs first
    const int bh   = blockIdx.y;
    const int row0 = qt * 128;
    const size_t bbase = (size_t)bh * SS * HD;
    const int ntiles = 2 * qt + 2;
    const int wrow_max = row0 + wid * 16 + 15;       // warp's highest q-row

    // ---- Q fragments (fp16, single), loaded once from gmem
    uint32_t aq[8][4];
    {
        const int r0 = row0 + wid * 16 + (lane >> 2);
        const __half* p0 = g_q16 + bbase + (size_t)r0 * HD + (lane & 3) * 2;
#pragma unroll
        for (int c = 0; c < 8; c++) {
            aq[c][0] = *(const uint32_t*)(p0 + c * 16);
            aq[c][1] = *(const uint32_t*)(p0 + 8 * HD + c * 16);
            aq[c][2] = *(const uint32_t*)(p0 + c * 16 + 8);
            aq[c][3] = *(const uint32_t*)(p0 + 8 * HD + c * 16 + 8);
        }
    }

    float ctx[16][4];
#pragma unroll
    for (int i = 0; i < 16; i++)
#pragma unroll
        for (int j = 0; j < 4; j++) ctx[i][j] = 0.f;
    float mrun0 = -1e30f, mrun1 = -1e30f, lrun0 = 0.f, lrun1 = 0.f;

    auto load_kv = [&](int stage, int j0) {
        const uint32_t base = sb + stage * STGKV;
        const __half* s0 = g_k16h + bbase + (size_t)j0 * HD;
        const __half* s1 = g_k16l + bbase + (size_t)j0 * HD;
        const __half* s2 = g_v16  + bbase + (size_t)j0 * HD;
#pragma unroll
        for (int it = 0; it < 12; it++) {
            const int arr = it / 4;
            const int r   = (it & 3) * 16 + (tid >> 4);
            const int ch  = tid & 15;
            const __half* g =
                (arr == 0 ? s0 : arr == 1 ? s1 : s2) + (size_t)r * HD + ch * 8;
            CP_ASYNC16(base + arr * TILEKV + r * SROW + ch * 16, g);
        }
    };

    load_kv(0, 0);
    CP_COMMIT();

    for (int t = 0; t < ntiles; t++) {
        const int j0  = t * KT2;
        const int cur = t & 1;
        CP_WAIT0();
        __syncthreads();
        if (t + 1 < ntiles) { load_kv(cur ^ 1, (t + 1) * KT2); CP_COMMIT(); }

        if (j0 <= wrow_max) {   // skip tiles fully above this warp's rows
            const uint32_t khb = sb + cur * STGKV;
            const uint32_t klb = khb + TILEKV;
            const uint32_t vb  = khb + 2 * TILEKV;

            // ---- scores: S = Q*Kh + Q*Kl  (hi pass then lo pass per c)
            float s[8][4];
#pragma unroll
            for (int i = 0; i < 8; i++)
#pragma unroll
                for (int j = 0; j < 4; j++) s[i][j] = 0.f;
#pragma unroll
            for (int c = 0; c < 8; c++) {
                const uint32_t koff = c * 32 + (lane >> 4) * 16;
                uint32_t bkh[4][4], bkl[4][4];
#pragma unroll
                for (int ng = 0; ng < 4; ng++) {
                    const uint32_t ra = (ng * 16 + (lane & 15)) * SROW + koff;
                    ldsm4(bkh[ng], khb + ra);
                    ldsm4(bkl[ng], klb + ra);
                }
#pragma unroll
                for (int prod = 0; prod < 2; prod++) {
                    const uint32_t (*bf)[4] = prod ? bkl : bkh;
#pragma unroll
                    for (int ng = 0; ng < 4; ng++) {
                        mma16816h(s[2 * ng],     aq[c], bf[ng][0], bf[ng][2]);
                        mma16816h(s[2 * ng + 1], aq[c], bf[ng][1], bf[ng][3]);
                    }
                }
            }

            // ---- scale (log2 domain) + causal mask
#pragma unroll
            for (int nf = 0; nf < 8; nf++)
#pragma unroll
                for (int j = 0; j < 4; j++) s[nf][j] *= KEXP;
            const int qr = row0 + wid * 16 + (lane >> 2);
            if (j0 + KT2 - 1 > row0) {
#pragma unroll
                for (int nf = 0; nf < 8; nf++) {
                    const int j = j0 + nf * 8 + (lane & 3) * 2;
                    if (j     > qr)     s[nf][0] = -1e30f;
                    if (j + 1 > qr)     s[nf][1] = -1e30f;
                    if (j     > qr + 8) s[nf][2] = -1e30f;
                    if (j + 1 > qr + 8) s[nf][3] = -1e30f;
                }
            }

            // ---- online softmax
            float mx0 = -1e30f, mx1 = -1e30f;
#pragma unroll
            for (int nf = 0; nf < 8; nf++) {
                mx0 = fmaxf(mx0, fmaxf(s[nf][0], s[nf][1]));
                mx1 = fmaxf(mx1, fmaxf(s[nf][2], s[nf][3]));
            }
            mx0 = fmaxf(mx0, __shfl_xor_sync(0xffffffff, mx0, 1));
            mx0 = fmaxf(mx0, __shfl_xor_sync(0xffffffff, mx0, 2));
            mx1 = fmaxf(mx1, __shfl_xor_sync(0xffffffff, mx1, 1));
            mx1 = fmaxf(mx1, __shfl_xor_sync(0xffffffff, mx1, 2));
            const float mn0 = fmaxf(mrun0, mx0), mn1 = fmaxf(mrun1, mx1);
            const float corr0 = ex2(mrun0 - mn0), corr1 = ex2(mrun1 - mn1);
            mrun0 = mn0; mrun1 = mn1;
            lrun0 *= corr0; lrun1 *= corr1;
#pragma unroll
            for (int nf = 0; nf < 16; nf++) {
                ctx[nf][0] *= corr0; ctx[nf][1] *= corr0;
                ctx[nf][2] *= corr1; ctx[nf][3] *= corr1;
            }

            // ---- P = exp2(s - m), pack fp16 A fragments (single)
            uint32_t ap[4][4];
            float ps0 = 0.f, ps1 = 0.f;
#pragma unroll
            for (int nf = 0; nf < 8; nf++) {
                const float p0 = ex2(s[nf][0] - mn0), p1 = ex2(s[nf][1] - mn0);
                const float p2 = ex2(s[nf][2] - mn1), p3 = ex2(s[nf][3] - mn1);
                ps0 += p0 + p1; ps1 += p2 + p3;
                const int kc = nf >> 1, hf = nf & 1;
                ap[kc][2 * hf]     = pack2h(p0, p1);
                ap[kc][2 * hf + 1] = pack2h(p2, p3);
            }
            lrun0 += ps0; lrun1 += ps1;

            // ---- ctx += P*V  (V via ldmatrix.trans; ctx reuse distance 16)
#pragma unroll
            for (int kc = 0; kc < 4; kc++) {
#pragma unroll
                for (int np = 0; np < 8; np++) {
                    const uint32_t av = (kc * 16 + ((lane >> 3) & 1) * 8 + (lane & 7)) * SROW
                                      + ((lane >> 4) * 16 + np * 32);
                    uint32_t bv[4];
                    ldsm4t(bv, vb + av);
                    mma16816h(ctx[2 * np],     ap[kc], bv[0], bv[1]);
                    mma16816h(ctx[2 * np + 1], ap[kc], bv[2], bv[3]);
                }
            }
        }
        __syncthreads();
    }

    // ---- epilogue: normalize, store fp16 ctx
    lrun0 += __shfl_xor_sync(0xffffffff, lrun0, 1);
    lrun0 += __shfl_xor_sync(0xffffffff, lrun0, 2);
    lrun1 += __shfl_xor_sync(0xffffffff, lrun1, 1);
    lrun1 += __shfl_xor_sync(0xffffffff, lrun1, 2);
    const float inv0 = 1.f / lrun0, inv1 = 1.f / lrun1;
    const int q0 = row0 + wid * 16 + (lane >> 2);
    const int b = bh >> 4, h = bh & 15;
#pragma unroll
    for (int nf = 0; nf < 16; nf++) {
        const int d = nf * 8 + (lane & 3) * 2;
        const size_t o0 = (size_t)(b * SS + q0) * DD + h * HD + d;
        const size_t o1 = o0 + (size_t)8 * DD;
        *(uint32_t*)(g_cth + o0) = pack2h(ctx[nf][0] * inv0, ctx[nf][1] * inv0);
        *(uint32_t*)(g_cth + o1) = pack2h(ctx[nf][2] * inv1, ctx[nf][3] * inv1);
    }
}

// ---------------------------------------------------------------------------
// Launch
// ---------------------------------------------------------------------------
extern "C" void kernel_launch(void* const* d_in, const int* in_sizes, int n_in,
                              void* d_out, int out_size)
{
    (void)in_sizes; (void)n_in; (void)out_size;
    const float* x  = (const float*)d_in[0];
    const float* Wq = (const float*)d_in[1];
    const float* Wk = (const float*)d_in[2];
    const float* Wv = (const float*)d_in[3];
    const float* Wo = (const float*)d_in[4];
    const float* bo = (const float*)d_in[5];
    float* out = (float*)d_out;

    cudaFuncSetAttribute(gemm_tc, cudaFuncAttributeMaxDynamicSharedMemorySize, GEMM_SMEM);
    cudaFuncSetAttribute(attn_tc, cudaFuncAttributeMaxDynamicSharedMemorySize, ATTN_SMEM);

    __half *xh_p, *cth_p;
    cudaGetSymbolAddress((void**)&xh_p, g_xh);
    cudaGetSymbolAddress((void**)&cth_p, g_cth);

    // 1. weight transpose + fp16 hi/lo split
    wtrans_split<<<dim3(DD/32, DD/32, 4), dim3(32, 8)>>>(Wq, Wk, Wv, Wo);
    // 2. round x to fp16
    round_fp16<<<(int)((size_t)MM*DD/4/256), 256>>>(x, xh_p);
    // 3. QKV projections (fp16 2-product) -> Q fp16 / K fp16 hi+lo / V fp16
    gemm_tc<<<dim3(DD/128, MM/128, 3), 256, GEMM_SMEM>>>(xh_p, nullptr, nullptr, 0);
    // 4. tensor-core flash attention (fp16, 2+1 products) -> fp16 ctx
    attn_tc<<<dim3(SS/128, BB*HH), 256, ATTN_SMEM>>>();
    // 5. output projection (fp16 2-product) + bias
    gemm_tc<<<dim3(DD/128, MM/128, 1), 256, GEMM_SMEM>>>(cth_p, out, bo, 1);
}

// round 12
// speedup vs baseline: 1.0951x; 1.0951x over previous
#include <cuda_runtime.h>
#include <cuda_bf16.h>
#include <cuda_fp16.h>
#include <cstdint>
#include <math.h>

// Problem constants
#define BB 2
#define SS 2048
#define DD 2048
#define HH 16
#define HD 128
#define MM (BB*SS)   // 4096

// ---------------------------------------------------------------------------
// Scratch (static device arrays)
// ---------------------------------------------------------------------------
__device__ __half g_xh[(size_t)MM*DD];                 // fp16-rounded x
__device__ __half g_cth[(size_t)MM*DD];                // fp16-rounded ctx
__device__ __half g_wh[4][(size_t)DD*DD];              // weights^T hi (fp16)
__device__ __half g_wl[4][(size_t)DD*DD];              // weights^T lo (fp16)
// Attention operands, layout [b*H+h][s][d]
__device__ __half g_q16[(size_t)BB*HH*SS*HD];          // Q fp16 (rounded)
__device__ __half g_k16h[(size_t)BB*HH*SS*HD];         // K fp16 hi (exact split)
__device__ __half g_k16l[(size_t)BB*HH*SS*HD];         // K fp16 lo
__device__ __half g_v16[(size_t)BB*HH*SS*HD];          // V fp16 (rounded)

// ---------------------------------------------------------------------------
// PTX helpers — baseline (sm_80+) instructions only (compute_103-safe)
// ---------------------------------------------------------------------------
__device__ __forceinline__ uint32_t smem_u32(const void* p) {
    uint32_t a;
    asm("{ .reg .u64 t; cvta.to.shared.u64 t, %1; cvt.u32.u64 %0, t; }" : "=r"(a) : "l"(p));
    return a;
}
#define CP_ASYNC16(dst, src) \
    asm volatile("cp.async.cg.shared.global [%0], [%1], 16;" :: "r"(dst), "l"(src))
#define CP_COMMIT() asm volatile("cp.async.commit_group;" ::: "memory")
#define CP_WAIT0()  asm volatile("cp.async.wait_group 0;" ::: "memory")

__device__ __forceinline__ void ldsm4(uint32_t* r, uint32_t a) {
    asm volatile("ldmatrix.sync.aligned.m8n8.x4.shared.b16 {%0,%1,%2,%3}, [%4];"
        : "=r"(r[0]), "=r"(r[1]), "=r"(r[2]), "=r"(r[3]) : "r"(a));
}
__device__ __forceinline__ void ldsm4t(uint32_t* r, uint32_t a) {
    asm volatile("ldmatrix.sync.aligned.m8n8.x4.trans.shared.b16 {%0,%1,%2,%3}, [%4];"
        : "=r"(r[0]), "=r"(r[1]), "=r"(r[2]), "=r"(r[3]) : "r"(a));
}
// fp16 MMA (all tensor work)
__device__ __forceinline__ void mma16816h(float* d, const uint32_t* a,
                                          uint32_t b0, uint32_t b1) {
    asm volatile(
        "mma.sync.aligned.m16n8k16.row.col.f32.f16.f16.f32 "
        "{%0,%1,%2,%3}, {%4,%5,%6,%7}, {%8,%9}, {%0,%1,%2,%3};"
        : "+f"(d[0]), "+f"(d[1]), "+f"(d[2]), "+f"(d[3])
        : "r"(a[0]), "r"(a[1]), "r"(a[2]), "r"(a[3]), "r"(b0), "r"(b1));
}
__device__ __forceinline__ float ex2(float x) {
    float r; asm("ex2.approx.f32 %0, %1;" : "=f"(r) : "f"(x)); return r;
}
// split two fp32 into packed fp16x2 hi and lo-residual
__device__ __forceinline__ void split2h(float v0, float v1, uint32_t& H, uint32_t& L) {
    __half h0 = __float2half_rn(v0), h1 = __float2half_rn(v1);
    float r0 = v0 - __half2float(h0), r1 = v1 - __half2float(h1);
    __half2 hh = __halves2half2(h0, h1);
    __half2 ll = __floats2half2_rn(r0, r1);
    H = *(uint32_t*)&hh;
    L = *(uint32_t*)&ll;
}
__device__ __forceinline__ uint32_t pack2h(float v0, float v1) {
    __half2 h = __floats2half2_rn(v0, v1);
    return *(uint32_t*)&h;
}

// ---------------------------------------------------------------------------
// fp32 -> fp16 round (elementwise, layout preserved)
// ---------------------------------------------------------------------------
__global__ void __launch_bounds__(256) round_fp16(const float* __restrict__ src,
                                                  __half* __restrict__ dst)
{
    size_t i = (size_t)blockIdx.x * blockDim.x + threadIdx.x;   // per float4
    float4 v = ((const float4*)src)[i];
    ((__half2*)dst)[2*i]   = __floats2half2_rn(v.x, v.y);
    ((__half2*)dst)[2*i+1] = __floats2half2_rn(v.z, v.w);
}

// ---------------------------------------------------------------------------
// Weight transpose + fp16 hi/lo split: W[K,N] fp32 -> Wt hi/lo [N,K] fp16
// ---------------------------------------------------------------------------
__global__ void __launch_bounds__(256) wtrans_split(const float* __restrict__ W0,
                                                    const float* __restrict__ W1,
                                                    const float* __restrict__ W2,
                                                    const float* __restrict__ W3)
{
    int z = blockIdx.z;
    const float* W = (z == 0) ? W0 : (z == 1) ? W1 : (z == 2) ? W2 : W3;
    __half* Th = g_wh[z];
    __half* Tl = g_wl[z];
    __shared__ float t[32][33];
    int tx = threadIdx.x, ty = threadIdx.y;
    int x  = blockIdx.x * 32 + tx;
    int y0 = blockIdx.y * 32;
#pragma unroll
    for (int r = 0; r < 4; r++)
        t[ty + r*8][tx] = W[(size_t)(y0 + ty + r*8) * DD + x];
    __syncthreads();
    int xo  = y0 + tx;
    int yo0 = blockIdx.x * 32;
#pragma unroll
    for (int r = 0; r < 4; r++) {
        float v = t[tx][ty + r*8];
        __half h = __float2half_rn(v);
        float res = v - __half2float(h);
        size_t o = (size_t)(yo0 + ty + r*8) * DD + xo;
        Th[o] = h;
        Tl[o] = __float2half_rn(res);
    }
}

// ---------------------------------------------------------------------------
// HMMA fp16 2-product GEMM: C[M,N] = A[M,K] @ Wt^T (Wt stored [N,K])
//   A = fp16-rounded activations; W split exactly: C = A*Wh + A*Wl
// Tile 128x128, KC=64 (half the barriers of KC=32), 2-stage cp.async,
// 8 warps x (32x64), 2 CTA/SM.
// mode 0: QKV proj -> Q fp16 / K fp16 hi+lo / V fp16. mode 1: out proj + bias.
// ---------------------------------------------------------------------------
#define KC 64
#define NCH (DD / KC)          // 32
#define ROWB 144               // smem bytes per row (128B data + 16B pad)
#define TILE_B (128 * ROWB)    // 18432
#define STAGE_B (3 * TILE_B)   // 55296 (A, Wh, Wl)
#define GEMM_SMEM (2 * STAGE_B) // 110592 -> 2 CTA/SM = 216KB

__global__ void __launch_bounds__(256, 2) gemm_tc(const __half* __restrict__ A,
                                                  float* __restrict__ out1,
                                                  const float* __restrict__ bias,
                                                  int mode)
{
    extern __shared__ char smc[];
    const uint32_t sb = smem_u32(smc);
    const int tid  = threadIdx.x;
    const int wid  = tid >> 5;
    const int lane = tid & 31;
    const int z    = blockIdx.z;
    const __half* Bh = g_wh[(mode == 0) ? z : 3];
    const __half* Bl = g_wl[(mode == 0) ? z : 3];
    const int row0 = blockIdx.y * 128;
    const int col0 = blockIdx.x * 128;
    const int mw   = (wid & 3) * 32;      // warp M offset in tile
    const int nw   = (wid >> 2) * 64;     // warp N offset in tile

    float acc[2][8][4];
#pragma unroll
    for (int i = 0; i < 2; i++)
#pragma unroll
        for (int j = 0; j < 8; j++)
#pragma unroll
            for (int q = 0; q < 4; q++) acc[i][j][q] = 0.f;

    // stage loader: 3 tiles x 128 rows x 8 chunks(16B) = 3072 cp.async
    auto load_stage = [&](int stage, int c) {
        const int k0 = c * KC;
        const uint32_t base = sb + stage * STAGE_B;
#pragma unroll
        for (int j = 0; j < 12; j++) {
            int i    = tid + j * 256;
            int tile = i >> 10;           // uniform per j (1024 per tile)
            int r    = (i >> 3) & 127;
            int ch   = i & 7;
            const __half* g;
            if      (tile == 0) g = A  + (size_t)(row0 + r) * DD + k0 + ch * 8;
            else if (tile == 1) g = Bh + (size_t)(col0 + r) * DD + k0 + ch * 8;
            else                g = Bl + (size_t)(col0 + r) * DD + k0 + ch * 8;
            CP_ASYNC16(base + tile * TILE_B + r * ROWB + ch * 16, g);
        }
    };

    load_stage(0, 0);
    CP_COMMIT();

    for (int c = 0; c < NCH; c++) {
        CP_WAIT0();
        __syncthreads();
        if (c + 1 < NCH) load_stage((c + 1) & 1, c + 1);
        CP_COMMIT();
        const uint32_t st = sb + (c & 1) * STAGE_B;

#pragma unroll
        for (int k16 = 0; k16 < 4; k16++) {
            const uint32_t koff = k16 * 32 + (lane >> 4) * 16;
            uint32_t af[2][4];
#pragma unroll
            for (int mm = 0; mm < 2; mm++) {
                const uint32_t ra = (mw + mm * 16 + (lane & 15)) * ROWB + koff;
                ldsm4(af[mm], st + ra);
            }
#pragma unroll
            for (int half = 0; half < 2; half++) {
                uint32_t bfh[2][4], bfl[2][4];
#pragma unroll
                for (int g2 = 0; g2 < 2; g2++) {
                    const int ng = half * 2 + g2;
                    const uint32_t rb = (nw + ng * 16 + (lane & 15)) * ROWB + koff;
                    ldsm4(bfh[g2], st + TILE_B + rb);
                    ldsm4(bfl[g2], st + 2 * TILE_B + rb);
                }
#pragma unroll
                for (int prod = 0; prod < 2; prod++) {
                    const uint32_t (*bf)[4] = prod ? bfl : bfh;
#pragma unroll
                    for (int mm = 0; mm < 2; mm++)
#pragma unroll
                        for (int g2 = 0; g2 < 2; g2++) {
                            const int ng = half * 2 + g2;
                            mma16816h(acc[mm][ng * 2],     af[mm], bf[g2][0], bf[g2][2]);
                            mma16816h(acc[mm][ng * 2 + 1], af[mm], bf[g2][1], bf[g2][3]);
                        }
                }
            }
        }
    }

    // ---- epilogue
#pragma unroll
    for (int mm = 0; mm < 2; mm++) {
        const int m0 = row0 + mw + mm * 16 + (lane >> 2);
#pragma unroll
        for (int ng = 0; ng < 4; ng++)
#pragma unroll
            for (int hf = 0; hf < 2; hf++) {
                const int n = col0 + nw + ng * 16 + hf * 8 + 2 * (lane & 3);
                const float* d = acc[mm][ng * 2 + hf];
                if (mode == 0) {
                    const int h = n >> 7;
#pragma unroll
                    for (int rr = 0; rr < 2; rr++) {
                        const int m = m0 + rr * 8;
                        const int b = m >> 11, s = m & 2047;
                        size_t off = ((size_t)(b * HH + h) * SS + s) * HD + (n & 127);
                        if (z == 0) {
                            *(uint32_t*)(g_q16 + off) = pack2h(d[rr*2], d[rr*2+1]);
                        } else if (z == 1) {
                            uint32_t Hh, Ll;
                            split2h(d[rr*2], d[rr*2+1], Hh, Ll);
                            *(uint32_t*)(g_k16h + off) = Hh;
                            *(uint32_t*)(g_k16l + off) = Ll;
                        } else {
                            *(uint32_t*)(g_v16 + off) = pack2h(d[rr*2], d[rr*2+1]);
                        }
                    }
                } else {
                    const float b0 = bias[n], b1 = bias[n + 1];
#pragma unroll
                    for (int rr = 0; rr < 2; rr++) {
                        const int m = m0 + rr * 8;
                        *(float2*)(out1 + (size_t)m * DD + n) =
                            make_float2(d[rr * 2] + b0, d[rr * 2 + 1] + b1);
                    }
                }
            }
    }
}

// ---------------------------------------------------------------------------
// Tensor-core flash attention (causal), fp16 — unchanged from R10/R11:
//   S = Q*(Kh+Kl) [2 products], ctx = P*V [1 product]
// ---------------------------------------------------------------------------
#define KT2 64
#define SROW 272
#define TILEKV (KT2 * SROW)
#define STGKV (3 * TILEKV)             // Kh, Kl, V
#define ATTN_SMEM (2 * STGKV)          // 104448
#define KEXP 0.12751744f               // 1/sqrt(128) * log2(e)

__global__ void __launch_bounds__(256, 1) attn_tc()
{
    extern __shared__ char smc[];
    const uint32_t sb = smem_u32(smc);
    const int tid = threadIdx.x, wid = tid >> 5, lane = tid & 31;
    const int qt   = (SS / 128 - 1) - blockIdx.x;    // longest CTAs first
    const int bh   = blockIdx.y;
    const int row0 = qt * 128;
    const size_t bbase = (size_t)bh * SS * HD;
    const int ntiles = 2 * qt + 2;
    const int wrow_max = row0 + wid * 16 + 15;       // warp's highest q-row

    // ---- Q fragments (fp16, single), loaded once from gmem
    uint32_t aq[8][4];
    {
        const int r0 = row0 + wid * 16 + (lane >> 2);
        const __half* p0 = g_q16 + bbase + (size_t)r0 * HD + (lane & 3) * 2;
#pragma unroll
        for (int c = 0; c < 8; c++) {
            aq[c][0] = *(const uint32_t*)(p0 + c * 16);
            aq[c][1] = *(const uint32_t*)(p0 + 8 * HD + c * 16);
            aq[c][2] = *(const uint32_t*)(p0 + c * 16 + 8);
            aq[c][3] = *(const uint32_t*)(p0 + 8 * HD + c * 16 + 8);
        }
    }

    float ctx[16][4];
#pragma unroll
    for (int i = 0; i < 16; i++)
#pragma unroll
        for (int j = 0; j < 4; j++) ctx[i][j] = 0.f;
    float mrun0 = -1e30f, mrun1 = -1e30f, lrun0 = 0.f, lrun1 = 0.f;

    auto load_kv = [&](int stage, int j0) {
        const uint32_t base = sb + stage * STGKV;
        const __half* s0 = g_k16h + bbase + (size_t)j0 * HD;
        const __half* s1 = g_k16l + bbase + (size_t)j0 * HD;
        const __half* s2 = g_v16  + bbase + (size_t)j0 * HD;
#pragma unroll
        for (int it = 0; it < 12; it++) {
            const int arr = it / 4;
            const int r   = (it & 3) * 16 + (tid >> 4);
            const int ch  = tid & 15;
            const __half* g =
                (arr == 0 ? s0 : arr == 1 ? s1 : s2) + (size_t)r * HD + ch * 8;
            CP_ASYNC16(base + arr * TILEKV + r * SROW + ch * 16, g);
        }
    };

    load_kv(0, 0);
    CP_COMMIT();

    for (int t = 0; t < ntiles; t++) {
        const int j0  = t * KT2;
        const int cur = t & 1;
        CP_WAIT0();
        __syncthreads();
        if (t + 1 < ntiles) { load_kv(cur ^ 1, (t + 1) * KT2); CP_COMMIT(); }

        if (j0 <= wrow_max) {   // skip tiles fully above this warp's rows
            const uint32_t khb = sb + cur * STGKV;
            const uint32_t klb = khb + TILEKV;
            const uint32_t vb  = khb + 2 * TILEKV;

            // ---- scores: S = Q*Kh + Q*Kl
            float s[8][4];
#pragma unroll
            for (int i = 0; i < 8; i++)
#pragma unroll
                for (int j = 0; j < 4; j++) s[i][j] = 0.f;
#pragma unroll
            for (int c = 0; c < 8; c++) {
                const uint32_t koff = c * 32 + (lane >> 4) * 16;
                uint32_t bkh[4][4], bkl[4][4];
#pragma unroll
                for (int ng = 0; ng < 4; ng++) {
                    const uint32_t ra = (ng * 16 + (lane & 15)) * SROW + koff;
                    ldsm4(bkh[ng], khb + ra);
                    ldsm4(bkl[ng], klb + ra);
                }
#pragma unroll
                for (int prod = 0; prod < 2; prod++) {
                    const uint32_t (*bf)[4] = prod ? bkl : bkh;
#pragma unroll
                    for (int ng = 0; ng < 4; ng++) {
                        mma16816h(s[2 * ng],     aq[c], bf[ng][0], bf[ng][2]);
                        mma16816h(s[2 * ng + 1], aq[c], bf[ng][1], bf[ng][3]);
                    }
                }
            }

            // ---- scale (log2 domain) + causal mask
#pragma unroll
            for (int nf = 0; nf < 8; nf++)
#pragma unroll
                for (int j = 0; j < 4; j++) s[nf][j] *= KEXP;
            const int qr = row0 + wid * 16 + (lane >> 2);
            if (j0 + KT2 - 1 > row0) {
#pragma unroll
                for (int nf = 0; nf < 8; nf++) {
                    const int j = j0 + nf * 8 + (lane & 3) * 2;
                    if (j     > qr)     s[nf][0] = -1e30f;
                    if (j + 1 > qr)     s[nf][1] = -1e30f;
                    if (j     > qr + 8) s[nf][2] = -1e30f;
                    if (j + 1 > qr + 8) s[nf][3] = -1e30f;
                }
            }

            // ---- online softmax
            float mx0 = -1e30f, mx1 = -1e30f;
#pragma unroll
            for (int nf = 0; nf < 8; nf++) {
                mx0 = fmaxf(mx0, fmaxf(s[nf][0], s[nf][1]));
                mx1 = fmaxf(mx1, fmaxf(s[nf][2], s[nf][3]));
            }
            mx0 = fmaxf(mx0, __shfl_xor_sync(0xffffffff, mx0, 1));
            mx0 = fmaxf(mx0, __shfl_xor_sync(0xffffffff, mx0, 2));
            mx1 = fmaxf(mx1, __shfl_xor_sync(0xffffffff, mx1, 1));
            mx1 = fmaxf(mx1, __shfl_xor_sync(0xffffffff, mx1, 2));
            const float mn0 = fmaxf(mrun0, mx0), mn1 = fmaxf(mrun1, mx1);
            const float corr0 = ex2(mrun0 - mn0), corr1 = ex2(mrun1 - mn1);
            mrun0 = mn0; mrun1 = mn1;
            lrun0 *= corr0; lrun1 *= corr1;
#pragma unroll
            for (int nf = 0; nf < 16; nf++) {
                ctx[nf][0] *= corr0; ctx[nf][1] *= corr0;
                ctx[nf][2] *= corr1; ctx[nf][3] *= corr1;
            }

            // ---- P = exp2(s - m), pack fp16 A fragments (single)
            uint32_t ap[4][4];
            float ps0 = 0.f, ps1 = 0.f;
#pragma unroll
            for (int nf = 0; nf < 8; nf++) {
                const float p0 = ex2(s[nf][0] - mn0), p1 = ex2(s[nf][1] - mn0);
                const float p2 = ex2(s[nf][2] - mn1), p3 = ex2(s[nf][3] - mn1);
                ps0 += p0 + p1; ps1 += p2 + p3;
                const int kc = nf >> 1, hf = nf & 1;
                ap[kc][2 * hf]     = pack2h(p0, p1);
                ap[kc][2 * hf + 1] = pack2h(p2, p3);
            }
            lrun0 += ps0; lrun1 += ps1;

            // ---- ctx += P*V  (V via ldmatrix.trans)
#pragma unroll
            for (int kc = 0; kc < 4; kc++) {
#pragma unroll
                for (int np = 0; np < 8; np++) {
                    const uint32_t av = (kc * 16 + ((lane >> 3) & 1) * 8 + (lane & 7)) * SROW
                                      + ((lane >> 4) * 16 + np * 32);
                    uint32_t bv[4];
                    ldsm4t(bv, vb + av);
                    mma16816h(ctx[2 * np],     ap[kc], bv[0], bv[1]);
                    mma16816h(ctx[2 * np + 1], ap[kc], bv[2], bv[3]);
                }
            }
        }
        __syncthreads();
    }

    // ---- epilogue: normalize, store fp16 ctx
    lrun0 += __shfl_xor_sync(0xffffffff, lrun0, 1);
    lrun0 += __shfl_xor_sync(0xffffffff, lrun0, 2);
    lrun1 += __shfl_xor_sync(0xffffffff, lrun1, 1);
    lrun1 += __shfl_xor_sync(0xffffffff, lrun1, 2);
    const float inv0 = 1.f / lrun0, inv1 = 1.f / lrun1;
    const int q0 = row0 + wid * 16 + (lane >> 2);
    const int b = bh >> 4, h = bh & 15;
#pragma unroll
    for (int nf = 0; nf < 16; nf++) {
        const int d = nf * 8 + (lane & 3) * 2;
        const size_t o0 = (size_t)(b * SS + q0) * DD + h * HD + d;
        const size_t o1 = o0 + (size_t)8 * DD;
        *(uint32_t*)(g_cth + o0) = pack2h(ctx[nf][0] * inv0, ctx[nf][1] * inv0);
        *(uint32_t*)(g_cth + o1) = pack2h(ctx[nf][2] * inv1, ctx[nf][3] * inv1);
    }
}

// ---------------------------------------------------------------------------
// Launch
// ---------------------------------------------------------------------------
extern "C" void kernel_launch(void* const* d_in, const int* in_sizes, int n_in,
                              void* d_out, int out_size)
{
    (void)in_sizes; (void)n_in; (void)out_size;
    const float* x  = (const float*)d_in[0];
    const float* Wq = (const float*)d_in[1];
    const float* Wk = (const float*)d_in[2];
    const float* Wv = (const float*)d_in[3];
    const float* Wo = (const float*)d_in[4];
    const float* bo = (const float*)d_in[5];
    float* out = (float*)d_out;

    cudaFuncSetAttribute(gemm_tc, cudaFuncAttributeMaxDynamicSharedMemorySize, GEMM_SMEM);
    cudaFuncSetAttribute(attn_tc, cudaFuncAttributeMaxDynamicSharedMemorySize, ATTN_SMEM);

    __half *xh_p, *cth_p;
    cudaGetSymbolAddress((void**)&xh_p, g_xh);
    cudaGetSymbolAddress((void**)&cth_p, g_cth);

    // 1. weight transpose + fp16 hi/lo split
    wtrans_split<<<dim3(DD/32, DD/32, 4), dim3(32, 8)>>>(Wq, Wk, Wv, Wo);
    // 2. round x to fp16
    round_fp16<<<(int)((size_t)MM*DD/4/256), 256>>>(x, xh_p);
    // 3. QKV projections (fp16 2-product, KC=64) -> Q / K hi+lo / V
    gemm_tc<<<dim3(DD/128, MM/128, 3), 256, GEMM_SMEM>>>(xh_p, nullptr, nullptr, 0);
    // 4. tensor-core flash attention (fp16, 2+1 products) -> fp16 ctx
    attn_tc<<<dim3(SS/128, BB*HH), 256, ATTN_SMEM>>>();
    // 5. output projection (fp16 2-product, KC=64) + bias
    gemm_tc<<<dim3(DD/128, MM/128, 1), 256, GEMM_SMEM>>>(cth_p, out, bo, 1);
}

// round 13
// speedup vs baseline: 1.1015x; 1.0059x over previous
#include <cuda_runtime.h>
#include <cuda_bf16.h>
#include <cuda_fp16.h>
#include <cstdint>
#include <math.h>

// Problem constants
#define BB 2
#define SS 2048
#define DD 2048
#define HH 16
#define HD 128
#define MM (BB*SS)   // 4096

// ---------------------------------------------------------------------------
// Scratch (static device arrays)
// ---------------------------------------------------------------------------
__device__ __half g_xh[(size_t)MM*DD];                 // fp16-rounded x
__device__ __half g_cth[(size_t)MM*DD];                // fp16-rounded ctx
__device__ __half g_wh[4][(size_t)DD*DD];              // weights^T hi (fp16)
__device__ __half g_wl[4][(size_t)DD*DD];              // weights^T lo (fp16)
// Attention operands, layout [b*H+h][s][d]
__device__ __half g_q16[(size_t)BB*HH*SS*HD];          // Q fp16 (rounded)
__device__ __half g_k16h[(size_t)BB*HH*SS*HD];         // K fp16 hi (exact split)
__device__ __half g_k16l[(size_t)BB*HH*SS*HD];         // K fp16 lo
__device__ __half g_v16[(size_t)BB*HH*SS*HD];          // V fp16 (rounded)

// ---------------------------------------------------------------------------
// PTX helpers — baseline (sm_80+) instructions only (compute_103-safe)
// ---------------------------------------------------------------------------
__device__ __forceinline__ uint32_t smem_u32(const void* p) {
    uint32_t a;
    asm("{ .reg .u64 t; cvta.to.shared.u64 t, %1; cvt.u32.u64 %0, t; }" : "=r"(a) : "l"(p));
    return a;
}
#define CP_ASYNC16(dst, src) \
    asm volatile("cp.async.cg.shared.global [%0], [%1], 16;" :: "r"(dst), "l"(src))
#define CP_COMMIT() asm volatile("cp.async.commit_group;" ::: "memory")
#define CP_WAIT0()  asm volatile("cp.async.wait_group 0;" ::: "memory")

__device__ __forceinline__ void ldsm4(uint32_t* r, uint32_t a) {
    asm volatile("ldmatrix.sync.aligned.m8n8.x4.shared.b16 {%0,%1,%2,%3}, [%4];"
        : "=r"(r[0]), "=r"(r[1]), "=r"(r[2]), "=r"(r[3]) : "r"(a));
}
__device__ __forceinline__ void ldsm4t(uint32_t* r, uint32_t a) {
    asm volatile("ldmatrix.sync.aligned.m8n8.x4.trans.shared.b16 {%0,%1,%2,%3}, [%4];"
        : "=r"(r[0]), "=r"(r[1]), "=r"(r[2]), "=r"(r[3]) : "r"(a));
}
// fp16 MMA (all tensor work)
__device__ __forceinline__ void mma16816h(float* d, const uint32_t* a,
                                          uint32_t b0, uint32_t b1) {
    asm volatile(
        "mma.sync.aligned.m16n8k16.row.col.f32.f16.f16.f32 "
        "{%0,%1,%2,%3}, {%4,%5,%6,%7}, {%8,%9}, {%0,%1,%2,%3};"
        : "+f"(d[0]), "+f"(d[1]), "+f"(d[2]), "+f"(d[3])
        : "r"(a[0]), "r"(a[1]), "r"(a[2]), "r"(a[3]), "r"(b0), "r"(b1));
}
__device__ __forceinline__ float ex2(float x) {
    float r; asm("ex2.approx.f32 %0, %1;" : "=f"(r) : "f"(x)); return r;
}
// split two fp32 into packed fp16x2 hi and lo-residual
__device__ __forceinline__ void split2h(float v0, float v1, uint32_t& H, uint32_t& L) {
    __half h0 = __float2half_rn(v0), h1 = __float2half_rn(v1);
    float r0 = v0 - __half2float(h0), r1 = v1 - __half2float(h1);
    __half2 hh = __halves2half2(h0, h1);
    __half2 ll = __floats2half2_rn(r0, r1);
    H = *(uint32_t*)&hh;
    L = *(uint32_t*)&ll;
}
__device__ __forceinline__ uint32_t pack2h(float v0, float v1) {
    __half2 h = __floats2half2_rn(v0, v1);
    return *(uint32_t*)&h;
}

// ---------------------------------------------------------------------------
// fp32 -> fp16 round (elementwise, layout preserved)
// ---------------------------------------------------------------------------
__global__ void __launch_bounds__(256) round_fp16(const float* __restrict__ src,
                                                  __half* __restrict__ dst)
{
    size_t i = (size_t)blockIdx.x * blockDim.x + threadIdx.x;   // per float4
    float4 v = ((const float4*)src)[i];
    ((__half2*)dst)[2*i]   = __floats2half2_rn(v.x, v.y);
    ((__half2*)dst)[2*i+1] = __floats2half2_rn(v.z, v.w);
}

// ---------------------------------------------------------------------------
// Weight transpose + fp16 hi/lo split: W[K,N] fp32 -> Wt hi/lo [N,K] fp16
// ---------------------------------------------------------------------------
__global__ void __launch_bounds__(256) wtrans_split(const float* __restrict__ W0,
                                                    const float* __restrict__ W1,
                                                    const float* __restrict__ W2,
                                                    const float* __restrict__ W3)
{
    int z = blockIdx.z;
    const float* W = (z == 0) ? W0 : (z == 1) ? W1 : (z == 2) ? W2 : W3;
    __half* Th = g_wh[z];
    __half* Tl = g_wl[z];
    __shared__ float t[32][33];
    int tx = threadIdx.x, ty = threadIdx.y;
    int x  = blockIdx.x * 32 + tx;
    int y0 = blockIdx.y * 32;
#pragma unroll
    for (int r = 0; r < 4; r++)
        t[ty + r*8][tx] = W[(size_t)(y0 + ty + r*8) * DD + x];
    __syncthreads();
    int xo  = y0 + tx;
    int yo0 = blockIdx.x * 32;
#pragma unroll
    for (int r = 0; r < 4; r++) {
        float v = t[tx][ty + r*8];
        __half h = __float2half_rn(v);
        float res = v - __half2float(h);
        size_t o = (size_t)(yo0 + ty + r*8) * DD + xo;
        Th[o] = h;
        Tl[o] = __float2half_rn(res);
    }
}

// ---------------------------------------------------------------------------
// HMMA fp16 2-product GEMM — unchanged from R12 (KC=64, 2 CTA/SM)
// ---------------------------------------------------------------------------
#define KC 64
#define NCH (DD / KC)          // 32
#define ROWB 144               // smem bytes per row (128B data + 16B pad)
#define TILE_B (128 * ROWB)    // 18432
#define STAGE_B (3 * TILE_B)   // 55296 (A, Wh, Wl)
#define GEMM_SMEM (2 * STAGE_B) // 110592 -> 2 CTA/SM = 216KB

__global__ void __launch_bounds__(256, 2) gemm_tc(const __half* __restrict__ A,
                                                  float* __restrict__ out1,
                                                  const float* __restrict__ bias,
                                                  int mode)
{
    extern __shared__ char smc[];
    const uint32_t sb = smem_u32(smc);
    const int tid  = threadIdx.x;
    const int wid  = tid >> 5;
    const int lane = tid & 31;
    const int z    = blockIdx.z;
    const __half* Bh = g_wh[(mode == 0) ? z : 3];
    const __half* Bl = g_wl[(mode == 0) ? z : 3];
    const int row0 = blockIdx.y * 128;
    const int col0 = blockIdx.x * 128;
    const int mw   = (wid & 3) * 32;      // warp M offset in tile
    const int nw   = (wid >> 2) * 64;     // warp N offset in tile

    float acc[2][8][4];
#pragma unroll
    for (int i = 0; i < 2; i++)
#pragma unroll
        for (int j = 0; j < 8; j++)
#pragma unroll
            for (int q = 0; q < 4; q++) acc[i][j][q] = 0.f;

    auto load_stage = [&](int stage, int c) {
        const int k0 = c * KC;
        const uint32_t base = sb + stage * STAGE_B;
#pragma unroll
        for (int j = 0; j < 12; j++) {
            int i    = tid + j * 256;
            int tile = i >> 10;           // uniform per j (1024 per tile)
            int r    = (i >> 3) & 127;
            int ch   = i & 7;
            const __half* g;
            if      (tile == 0) g = A  + (size_t)(row0 + r) * DD + k0 + ch * 8;
            else if (tile == 1) g = Bh + (size_t)(col0 + r) * DD + k0 + ch * 8;
            else                g = Bl + (size_t)(col0 + r) * DD + k0 + ch * 8;
            CP_ASYNC16(base + tile * TILE_B + r * ROWB + ch * 16, g);
        }
    };

    load_stage(0, 0);
    CP_COMMIT();

    for (int c = 0; c < NCH; c++) {
        CP_WAIT0();
        __syncthreads();
        if (c + 1 < NCH) load_stage((c + 1) & 1, c + 1);
        CP_COMMIT();
        const uint32_t st = sb + (c & 1) * STAGE_B;

#pragma unroll
        for (int k16 = 0; k16 < 4; k16++) {
            const uint32_t koff = k16 * 32 + (lane >> 4) * 16;
            uint32_t af[2][4];
#pragma unroll
            for (int mm = 0; mm < 2; mm++) {
                const uint32_t ra = (mw + mm * 16 + (lane & 15)) * ROWB + koff;
                ldsm4(af[mm], st + ra);
            }
#pragma unroll
            for (int half = 0; half < 2; half++) {
                uint32_t bfh[2][4], bfl[2][4];
#pragma unroll
                for (int g2 = 0; g2 < 2; g2++) {
                    const int ng = half * 2 + g2;
                    const uint32_t rb = (nw + ng * 16 + (lane & 15)) * ROWB + koff;
                    ldsm4(bfh[g2], st + TILE_B + rb);
                    ldsm4(bfl[g2], st + 2 * TILE_B + rb);
                }
#pragma unroll
                for (int prod = 0; prod < 2; prod++) {
                    const uint32_t (*bf)[4] = prod ? bfl : bfh;
#pragma unroll
                    for (int mm = 0; mm < 2; mm++)
#pragma unroll
                        for (int g2 = 0; g2 < 2; g2++) {
                            const int ng = half * 2 + g2;
                            mma16816h(acc[mm][ng * 2],     af[mm], bf[g2][0], bf[g2][2]);
                            mma16816h(acc[mm][ng * 2 + 1], af[mm], bf[g2][1], bf[g2][3]);
                        }
                }
            }
        }
    }

    // ---- epilogue
#pragma unroll
    for (int mm = 0; mm < 2; mm++) {
        const int m0 = row0 + mw + mm * 16 + (lane >> 2);
#pragma unroll
        for (int ng = 0; ng < 4; ng++)
#pragma unroll
            for (int hf = 0; hf < 2; hf++) {
                const int n = col0 + nw + ng * 16 + hf * 8 + 2 * (lane & 3);
                const float* d = acc[mm][ng * 2 + hf];
                if (mode == 0) {
                    const int h = n >> 7;
#pragma unroll
                    for (int rr = 0; rr < 2; rr++) {
                        const int m = m0 + rr * 8;
                        const int b = m >> 11, s = m & 2047;
                        size_t off = ((size_t)(b * HH + h) * SS + s) * HD + (n & 127);
                        if (z == 0) {
                            *(uint32_t*)(g_q16 + off) = pack2h(d[rr*2], d[rr*2+1]);
                        } else if (z == 1) {
                            uint32_t Hh, Ll;
                            split2h(d[rr*2], d[rr*2+1], Hh, Ll);
                            *(uint32_t*)(g_k16h + off) = Hh;
                            *(uint32_t*)(g_k16l + off) = Ll;
                        } else {
                            *(uint32_t*)(g_v16 + off) = pack2h(d[rr*2], d[rr*2+1]);
                        }
                    }
                } else {
                    const float b0 = bias[n], b1 = bias[n + 1];
#pragma unroll
                    for (int rr = 0; rr < 2; rr++) {
                        const int m = m0 + rr * 8;
                        *(float2*)(out1 + (size_t)m * DD + n) =
                            make_float2(d[rr * 2] + b0, d[rr * 2 + 1] + b1);
                    }
                }
            }
    }
}

// ---------------------------------------------------------------------------
// Tensor-core flash attention (causal), fp16:
//   S = Q*(Kh+Kl) [2 products], ctx = P*V [1 product]
// NEW: KT2=128 key tiles — halves tile count, barriers, and per-tile
// softmax fixed overhead. 3 tiles (Kh,Kl,V) x 128 rows, 2 stages = 204KB.
// ---------------------------------------------------------------------------
#define KT2 128
#define SROW 272
#define TILEKV (KT2 * SROW)            // 34816
#define STGKV (3 * TILEKV)             // 104448 (Kh, Kl, V)
#define ATTN_SMEM (2 * STGKV)          // 208896
#define KEXP 0.12751744f               // 1/sqrt(128) * log2(e)

__global__ void __launch_bounds__(256, 1) attn_tc()
{
    extern __shared__ char smc[];
    const uint32_t sb = smem_u32(smc);
    const int tid = threadIdx.x, wid = tid >> 5, lane = tid & 31;
    const int qt   = (SS / 128 - 1) - blockIdx.x;    // longest CTAs first
    const int bh   = blockIdx.y;
    const int row0 = qt * 128;
    const size_t bbase = (size_t)bh * SS * HD;
    const int ntiles = qt + 1;

    // ---- Q fragments (fp16, single), loaded once from gmem
    uint32_t aq[8][4];
    {
        const int r0 = row0 + wid * 16 + (lane >> 2);
        const __half* p0 = g_q16 + bbase + (size_t)r0 * HD + (lane & 3) * 2;
#pragma unroll
        for (int c = 0; c < 8; c++) {
            aq[c][0] = *(const uint32_t*)(p0 + c * 16);
            aq[c][1] = *(const uint32_t*)(p0 + 8 * HD + c * 16);
            aq[c][2] = *(const uint32_t*)(p0 + c * 16 + 8);
            aq[c][3] = *(const uint32_t*)(p0 + 8 * HD + c * 16 + 8);
        }
    }

    float ctx[16][4];
#pragma unroll
    for (int i = 0; i < 16; i++)
#pragma unroll
        for (int j = 0; j < 4; j++) ctx[i][j] = 0.f;
    float mrun0 = -1e30f, mrun1 = -1e30f, lrun0 = 0.f, lrun1 = 0.f;

    // KV loader: 3 tiles x 128 rows x 16 chunks(16B) = 6144 cp.async / 256 thr
    auto load_kv = [&](int stage, int j0) {
        const uint32_t base = sb + stage * STGKV;
        const __half* s0 = g_k16h + bbase + (size_t)j0 * HD;
        const __half* s1 = g_k16l + bbase + (size_t)j0 * HD;
        const __half* s2 = g_v16  + bbase + (size_t)j0 * HD;
#pragma unroll
        for (int it = 0; it < 24; it++) {
            const int arr = it / 8;
            const int r   = (it & 7) * 16 + (tid >> 4);
            const int ch  = tid & 15;
            const __half* g =
                (arr == 0 ? s0 : arr == 1 ? s1 : s2) + (size_t)r * HD + ch * 8;
            CP_ASYNC16(base + arr * TILEKV + r * SROW + ch * 16, g);
        }
    };

    load_kv(0, 0);
    CP_COMMIT();

    for (int t = 0; t < ntiles; t++) {
        const int j0  = t * KT2;
        const int cur = t & 1;
        CP_WAIT0();
        __syncthreads();
        if (t + 1 < ntiles) { load_kv(cur ^ 1, (t + 1) * KT2); CP_COMMIT(); }

        const uint32_t khb = sb + cur * STGKV;
        const uint32_t klb = khb + TILEKV;
        const uint32_t vb  = khb + 2 * TILEKV;

        // ---- scores: S = Q*Kh + Q*Kl  (8 n-groups = 128 keys)
        float s[16][4];
#pragma unroll
        for (int i = 0; i < 16; i++)
#pragma unroll
            for (int j = 0; j < 4; j++) s[i][j] = 0.f;
#pragma unroll
        for (int c = 0; c < 8; c++) {
            const uint32_t koff = c * 32 + (lane >> 4) * 16;
#pragma unroll
            for (int half = 0; half < 2; half++) {
                uint32_t bkh[4][4], bkl[4][4];
#pragma unroll
                for (int g2 = 0; g2 < 4; g2++) {
                    const int ng = half * 4 + g2;
                    const uint32_t ra = (ng * 16 + (lane & 15)) * SROW + koff;
                    ldsm4(bkh[g2], khb + ra);
                    ldsm4(bkl[g2], klb + ra);
                }
#pragma unroll
                for (int prod = 0; prod < 2; prod++) {
                    const uint32_t (*bf)[4] = prod ? bkl : bkh;
#pragma unroll
                    for (int g2 = 0; g2 < 4; g2++) {
                        const int ng = half * 4 + g2;
                        mma16816h(s[2 * ng],     aq[c], bf[g2][0], bf[g2][2]);
                        mma16816h(s[2 * ng + 1], aq[c], bf[g2][1], bf[g2][3]);
                    }
                }
            }
        }

        // ---- scale (log2 domain) + causal mask (final/diagonal tile only)
#pragma unroll
        for (int nf = 0; nf < 16; nf++)
#pragma unroll
            for (int j = 0; j < 4; j++) s[nf][j] *= KEXP;
        const int qr = row0 + wid * 16 + (lane >> 2);
        if (t == ntiles - 1) {
#pragma unroll
            for (int nf = 0; nf < 16; nf++) {
                const int j = j0 + nf * 8 + (lane & 3) * 2;
                if (j     > qr)     s[nf][0] = -1e30f;
                if (j + 1 > qr)     s[nf][1] = -1e30f;
                if (j     > qr + 8) s[nf][2] = -1e30f;
                if (j + 1 > qr + 8) s[nf][3] = -1e30f;
            }
        }

        // ---- online softmax
        float mx0 = -1e30f, mx1 = -1e30f;
#pragma unroll
        for (int nf = 0; nf < 16; nf++) {
            mx0 = fmaxf(mx0, fmaxf(s[nf][0], s[nf][1]));
            mx1 = fmaxf(mx1, fmaxf(s[nf][2], s[nf][3]));
        }
        mx0 = fmaxf(mx0, __shfl_xor_sync(0xffffffff, mx0, 1));
        mx0 = fmaxf(mx0, __shfl_xor_sync(0xffffffff, mx0, 2));
        mx1 = fmaxf(mx1, __shfl_xor_sync(0xffffffff, mx1, 1));
        mx1 = fmaxf(mx1, __shfl_xor_sync(0xffffffff, mx1, 2));
        const float mn0 = fmaxf(mrun0, mx0), mn1 = fmaxf(mrun1, mx1);
        const float corr0 = ex2(mrun0 - mn0), corr1 = ex2(mrun1 - mn1);
        mrun0 = mn0; mrun1 = mn1;
        lrun0 *= corr0; lrun1 *= corr1;
#pragma unroll
        for (int nf = 0; nf < 16; nf++) {
            ctx[nf][0] *= corr0; ctx[nf][1] *= corr0;
            ctx[nf][2] *= corr1; ctx[nf][3] *= corr1;
        }

        // ---- P = exp2(s - m), pack fp16 A fragments (single)
        uint32_t ap[8][4];
        float ps0 = 0.f, ps1 = 0.f;
#pragma unroll
        for (int nf = 0; nf < 16; nf++) {
            const float p0 = ex2(s[nf][0] - mn0), p1 = ex2(s[nf][1] - mn0);
            const float p2 = ex2(s[nf][2] - mn1), p3 = ex2(s[nf][3] - mn1);
            ps0 += p0 + p1; ps1 += p2 + p3;
            const int kc = nf >> 1, hf = nf & 1;
            ap[kc][2 * hf]     = pack2h(p0, p1);
            ap[kc][2 * hf + 1] = pack2h(p2, p3);
        }
        lrun0 += ps0; lrun1 += ps1;

        // ---- ctx += P*V  (V via ldmatrix.trans, 8 k-chunks of 16 keys)
#pragma unroll
        for (int kc = 0; kc < 8; kc++) {
#pragma unroll
            for (int np = 0; np < 8; np++) {
                const uint32_t av = (kc * 16 + ((lane >> 3) & 1) * 8 + (lane & 7)) * SROW
                                  + ((lane >> 4) * 16 + np * 32);
                uint32_t bv[4];
                ldsm4t(bv, vb + av);
                mma16816h(ctx[2 * np],     ap[kc], bv[0], bv[1]);
                mma16816h(ctx[2 * np + 1], ap[kc], bv[2], bv[3]);
            }
        }
        __syncthreads();
    }

    // ---- epilogue: normalize, store fp16 ctx
    lrun0 += __shfl_xor_sync(0xffffffff, lrun0, 1);
    lrun0 += __shfl_xor_sync(0xffffffff, lrun0, 2);
    lrun1 += __shfl_xor_sync(0xffffffff, lrun1, 1);
    lrun1 += __shfl_xor_sync(0xffffffff, lrun1, 2);
    const float inv0 = 1.f / lrun0, inv1 = 1.f / lrun1;
    const int q0 = row0 + wid * 16 + (lane >> 2);
    const int b = bh >> 4, h = bh & 15;
#pragma unroll
    for (int nf = 0; nf < 16; nf++) {
        const int d = nf * 8 + (lane & 3) * 2;
        const size_t o0 = (size_t)(b * SS + q0) * DD + h * HD + d;
        const size_t o1 = o0 + (size_t)8 * DD;
        *(uint32_t*)(g_cth + o0) = pack2h(ctx[nf][0] * inv0, ctx[nf][1] * inv0);
        *(uint32_t*)(g_cth + o1) = pack2h(ctx[nf][2] * inv1, ctx[nf][3] * inv1);
    }
}

// ---------------------------------------------------------------------------
// Launch
// ---------------------------------------------------------------------------
extern "C" void kernel_launch(void* const* d_in, const int* in_sizes, int n_in,
                              void* d_out, int out_size)
{
    (void)in_sizes; (void)n_in; (void)out_size;
    const float* x  = (const float*)d_in[0];
    const float* Wq = (const float*)d_in[1];
    const float* Wk = (const float*)d_in[2];
    const float* Wv = (const float*)d_in[3];
    const float* Wo = (const float*)d_in[4];
    const float* bo = (const float*)d_in[5];
    float* out = (float*)d_out;

    cudaFuncSetAttribute(gemm_tc, cudaFuncAttributeMaxDynamicSharedMemorySize, GEMM_SMEM);
    cudaFuncSetAttribute(attn_tc, cudaFuncAttributeMaxDynamicSharedMemorySize, ATTN_SMEM);

    __half *xh_p, *cth_p;
    cudaGetSymbolAddress((void**)&xh_p, g_xh);
    cudaGetSymbolAddress((void**)&cth_p, g_cth);

    // 1. weight transpose + fp16 hi/lo split
    wtrans_split<<<dim3(DD/32, DD/32, 4), dim3(32, 8)>>>(Wq, Wk, Wv, Wo);
    // 2. round x to fp16
    round_fp16<<<(int)((size_t)MM*DD/4/256), 256>>>(x, xh_p);
    // 3. QKV projections (fp16 2-product, KC=64) -> Q / K hi+lo / V
    gemm_tc<<<dim3(DD/128, MM/128, 3), 256, GEMM_SMEM>>>(xh_p, nullptr, nullptr, 0);
    // 4. tensor-core flash attention (fp16, KT2=128) -> fp16 ctx
    attn_tc<<<dim3(SS/128, BB*HH), 256, ATTN_SMEM>>>();
    // 5. output projection (fp16 2-product, KC=64) + bias
    gemm_tc<<<dim3(DD/128, MM/128, 1), 256, GEMM_SMEM>>>(cth_p, out, bo, 1);
}

// round 14
// speedup vs baseline: 1.4192x; 1.2884x over previous
#include <cuda_runtime.h>
#include <cuda_bf16.h>
#include <cuda_fp16.h>
#include <cstdint>
#include <math.h>

// Problem constants
#define BB 2
#define SS 2048
#define DD 2048
#define HH 16
#define HD 128
#define MM (BB*SS)   // 4096

// ---------------------------------------------------------------------------
// Scratch (static device arrays)
// ---------------------------------------------------------------------------
__device__ __half g_xh[(size_t)MM*DD];                 // fp16-rounded x
__device__ __half g_cth[(size_t)MM*DD];                // fp16-rounded ctx
__device__ __half g_wh[4][(size_t)DD*DD];              // weights^T hi (fp16)
__device__ __half g_wl[4][(size_t)DD*DD];              // weights^T lo (fp16)
// Attention operands, layout [b*H+h][s][d]
__device__ __half g_q16[(size_t)BB*HH*SS*HD];          // Q fp16 (rounded)
__device__ __half g_k16h[(size_t)BB*HH*SS*HD];         // K fp16 hi (exact split)
__device__ __half g_k16l[(size_t)BB*HH*SS*HD];         // K fp16 lo
__device__ __half g_v16[(size_t)BB*HH*SS*HD];          // V fp16 (rounded)

// ---------------------------------------------------------------------------
// PTX helpers — baseline (sm_80+) instructions only (compute_103-safe)
// ---------------------------------------------------------------------------
__device__ __forceinline__ uint32_t smem_u32(const void* p) {
    uint32_t a;
    asm("{ .reg .u64 t; cvta.to.shared.u64 t, %1; cvt.u32.u64 %0, t; }" : "=r"(a) : "l"(p));
    return a;
}
#define CP_ASYNC16(dst, src) \
    asm volatile("cp.async.cg.shared.global [%0], [%1], 16;" :: "r"(dst), "l"(src))
#define CP_COMMIT() asm volatile("cp.async.commit_group;" ::: "memory")
#define CP_WAIT0()  asm volatile("cp.async.wait_group 0;" ::: "memory")

__device__ __forceinline__ void ldsm4(uint32_t* r, uint32_t a) {
    asm volatile("ldmatrix.sync.aligned.m8n8.x4.shared.b16 {%0,%1,%2,%3}, [%4];"
        : "=r"(r[0]), "=r"(r[1]), "=r"(r[2]), "=r"(r[3]) : "r"(a));
}
__device__ __forceinline__ void ldsm4t(uint32_t* r, uint32_t a) {
    asm volatile("ldmatrix.sync.aligned.m8n8.x4.trans.shared.b16 {%0,%1,%2,%3}, [%4];"
        : "=r"(r[0]), "=r"(r[1]), "=r"(r[2]), "=r"(r[3]) : "r"(a));
}
// fp16 MMA (all tensor work)
__device__ __forceinline__ void mma16816h(float* d, const uint32_t* a,
                                          uint32_t b0, uint32_t b1) {
    asm volatile(
        "mma.sync.aligned.m16n8k16.row.col.f32.f16.f16.f32 "
        "{%0,%1,%2,%3}, {%4,%5,%6,%7}, {%8,%9}, {%0,%1,%2,%3};"
        : "+f"(d[0]), "+f"(d[1]), "+f"(d[2]), "+f"(d[3])
        : "r"(a[0]), "r"(a[1]), "r"(a[2]), "r"(a[3]), "r"(b0), "r"(b1));
}
__device__ __forceinline__ float ex2(float x) {
    float r; asm("ex2.approx.f32 %0, %1;" : "=f"(r) : "f"(x)); return r;
}
// split two fp32 into packed fp16x2 hi and lo-residual
__device__ __forceinline__ void split2h(float v0, float v1, uint32_t& H, uint32_t& L) {
    __half h0 = __float2half_rn(v0), h1 = __float2half_rn(v1);
    float r0 = v0 - __half2float(h0), r1 = v1 - __half2float(h1);
    __half2 hh = __halves2half2(h0, h1);
    __half2 ll = __floats2half2_rn(r0, r1);
    H = *(uint32_t*)&hh;
    L = *(uint32_t*)&ll;
}
__device__ __forceinline__ uint32_t pack2h(float v0, float v1) {
    __half2 h = __floats2half2_rn(v0, v1);
    return *(uint32_t*)&h;
}

// ---------------------------------------------------------------------------
// fp32 -> fp16 round (elementwise, layout preserved)
// ---------------------------------------------------------------------------
__global__ void __launch_bounds__(256) round_fp16(const float* __restrict__ src,
                                                  __half* __restrict__ dst)
{
    size_t i = (size_t)blockIdx.x * blockDim.x + threadIdx.x;   // per float4
    float4 v = ((const float4*)src)[i];
    ((__half2*)dst)[2*i]   = __floats2half2_rn(v.x, v.y);
    ((__half2*)dst)[2*i+1] = __floats2half2_rn(v.z, v.w);
}

// ---------------------------------------------------------------------------
// Weight transpose + fp16 hi/lo split: W[K,N] fp32 -> Wt hi/lo [N,K] fp16
// ---------------------------------------------------------------------------
__global__ void __launch_bounds__(256) wtrans_split(const float* __restrict__ W0,
                                                    const float* __restrict__ W1,
                                                    const float* __restrict__ W2,
                                                    const float* __restrict__ W3)
{
    int z = blockIdx.z;
    const float* W = (z == 0) ? W0 : (z == 1) ? W1 : (z == 2) ? W2 : W3;
    __half* Th = g_wh[z];
    __half* Tl = g_wl[z];
    __shared__ float t[32][33];
    int tx = threadIdx.x, ty = threadIdx.y;
    int x  = blockIdx.x * 32 + tx;
    int y0 = blockIdx.y * 32;
#pragma unroll
    for (int r = 0; r < 4; r++)
        t[ty + r*8][tx] = W[(size_t)(y0 + ty + r*8) * DD + x];
    __syncthreads();
    int xo  = y0 + tx;
    int yo0 = blockIdx.x * 32;
#pragma unroll
    for (int r = 0; r < 4; r++) {
        float v = t[tx][ty + r*8];
        __half h = __float2half_rn(v);
        float res = v - __half2float(h);
        size_t o = (size_t)(yo0 + ty + r*8) * DD + xo;
        Th[o] = h;
        Tl[o] = __float2half_rn(res);
    }
}

// ---------------------------------------------------------------------------
// HMMA fp16 GEMM: C[M,N] = A[M,K] @ Wt^T (Wt stored [N,K])
// K-proj (mode 0, z==1): 2 products (A*Wh + A*Wl, exact weight split).
// Q-proj, V-proj, out-proj: 1 product (A*Wh) — linear/tolerant error paths.
// Tile 128x128, KC=64, 2-stage cp.async, 8 warps x (32x64), 2 CTA/SM.
// ---------------------------------------------------------------------------
#define KC 64
#define NCH (DD / KC)          // 32
#define ROWB 144               // smem bytes per row (128B data + 16B pad)
#define TILE_B (128 * ROWB)    // 18432
#define STAGE_B (3 * TILE_B)   // 55296 (A, Wh, Wl)
#define GEMM_SMEM (2 * STAGE_B) // 110592 -> 2 CTA/SM = 216KB

__global__ void __launch_bounds__(256, 2) gemm_tc(const __half* __restrict__ A,
                                                  float* __restrict__ out1,
                                                  const float* __restrict__ bias,
                                                  int mode)
{
    extern __shared__ char smc[];
    const uint32_t sb = smem_u32(smc);
    const int tid  = threadIdx.x;
    const int wid  = tid >> 5;
    const int lane = tid & 31;
    const int z    = blockIdx.z;
    const bool use_lo = (mode == 0) && (z == 1);   // K-proj only
    const __half* Bh = g_wh[(mode == 0) ? z : 3];
    const __half* Bl = g_wl[(mode == 0) ? z : 3];
    const int row0 = blockIdx.y * 128;
    const int col0 = blockIdx.x * 128;
    const int mw   = (wid & 3) * 32;      // warp M offset in tile
    const int nw   = (wid >> 2) * 64;     // warp N offset in tile

    float acc[2][8][4];
#pragma unroll
    for (int i = 0; i < 2; i++)
#pragma unroll
        for (int j = 0; j < 8; j++)
#pragma unroll
            for (int q = 0; q < 4; q++) acc[i][j][q] = 0.f;

    // stage loader: A + Wh always; Wl only when use_lo
    auto load_stage = [&](int stage, int c) {
        const int k0 = c * KC;
        const uint32_t base = sb + stage * STAGE_B;
#pragma unroll
        for (int j = 0; j < 12; j++) {
            if (j >= 8 && !use_lo) break;          // uniform branch
            int i    = tid + j * 256;
            int tile = i >> 10;           // uniform per j (1024 per tile)
            int r    = (i >> 3) & 127;
            int ch   = i & 7;
            const __half* g;
            if      (tile == 0) g = A  + (size_t)(row0 + r) * DD + k0 + ch * 8;
            else if (tile == 1) g = Bh + (size_t)(col0 + r) * DD + k0 + ch * 8;
            else                g = Bl + (size_t)(col0 + r) * DD + k0 + ch * 8;
            CP_ASYNC16(base + tile * TILE_B + r * ROWB + ch * 16, g);
        }
    };

    load_stage(0, 0);
    CP_COMMIT();

    for (int c = 0; c < NCH; c++) {
        CP_WAIT0();
        __syncthreads();
        if (c + 1 < NCH) load_stage((c + 1) & 1, c + 1);
        CP_COMMIT();
        const uint32_t st = sb + (c & 1) * STAGE_B;

#pragma unroll
        for (int k16 = 0; k16 < 4; k16++) {
            const uint32_t koff = k16 * 32 + (lane >> 4) * 16;
            uint32_t af[2][4];
#pragma unroll
            for (int mm = 0; mm < 2; mm++) {
                const uint32_t ra = (mw + mm * 16 + (lane & 15)) * ROWB + koff;
                ldsm4(af[mm], st + ra);
            }
#pragma unroll
            for (int half = 0; half < 2; half++) {
                uint32_t bfh[2][4], bfl[2][4];
#pragma unroll
                for (int g2 = 0; g2 < 2; g2++) {
                    const int ng = half * 2 + g2;
                    const uint32_t rb = (nw + ng * 16 + (lane & 15)) * ROWB + koff;
                    ldsm4(bfh[g2], st + TILE_B + rb);
                    if (use_lo) ldsm4(bfl[g2], st + 2 * TILE_B + rb);
                }
                // hi pass
#pragma unroll
                for (int mm = 0; mm < 2; mm++)
#pragma unroll
                    for (int g2 = 0; g2 < 2; g2++) {
                        const int ng = half * 2 + g2;
                        mma16816h(acc[mm][ng * 2],     af[mm], bfh[g2][0], bfh[g2][2]);
                        mma16816h(acc[mm][ng * 2 + 1], af[mm], bfh[g2][1], bfh[g2][3]);
                    }
                // lo pass (K-proj only)
                if (use_lo) {
#pragma unroll
                    for (int mm = 0; mm < 2; mm++)
#pragma unroll
                        for (int g2 = 0; g2 < 2; g2++) {
                            const int ng = half * 2 + g2;
                            mma16816h(acc[mm][ng * 2],     af[mm], bfl[g2][0], bfl[g2][2]);
                            mma16816h(acc[mm][ng * 2 + 1], af[mm], bfl[g2][1], bfl[g2][3]);
                        }
                }
            }
        }
    }

    // ---- epilogue
#pragma unroll
    for (int mm = 0; mm < 2; mm++) {
        const int m0 = row0 + mw + mm * 16 + (lane >> 2);
#pragma unroll
        for (int ng = 0; ng < 4; ng++)
#pragma unroll
            for (int hf = 0; hf < 2; hf++) {
                const int n = col0 + nw + ng * 16 + hf * 8 + 2 * (lane & 3);
                const float* d = acc[mm][ng * 2 + hf];
                if (mode == 0) {
                    const int h = n >> 7;
#pragma unroll
                    for (int rr = 0; rr < 2; rr++) {
                        const int m = m0 + rr * 8;
                        const int b = m >> 11, s = m & 2047;
                        size_t off = ((size_t)(b * HH + h) * SS + s) * HD + (n & 127);
                        if (z == 0) {
                            *(uint32_t*)(g_q16 + off) = pack2h(d[rr*2], d[rr*2+1]);
                        } else if (z == 1) {
                            uint32_t Hh, Ll;
                            split2h(d[rr*2], d[rr*2+1], Hh, Ll);
                            *(uint32_t*)(g_k16h + off) = Hh;
                            *(uint32_t*)(g_k16l + off) = Ll;
                        } else {
                            *(uint32_t*)(g_v16 + off) = pack2h(d[rr*2], d[rr*2+1]);
                        }
                    }
                } else {
                    const float b0 = bias[n], b1 = bias[n + 1];
#pragma unroll
                    for (int rr = 0; rr < 2; rr++) {
                        const int m = m0 + rr * 8;
                        *(float2*)(out1 + (size_t)m * DD + n) =
                            make_float2(d[rr * 2] + b0, d[rr * 2 + 1] + b1);
                    }
                }
            }
    }
}

// ---------------------------------------------------------------------------
// Tensor-core flash attention (causal), fp16 — unchanged from R13 (KT2=128):
//   S = Q*(Kh+Kl) [2 products], ctx = P*V [1 product]
// ---------------------------------------------------------------------------
#define KT2 128
#define SROW 272
#define TILEKV (KT2 * SROW)            // 34816
#define STGKV (3 * TILEKV)             // 104448 (Kh, Kl, V)
#define ATTN_SMEM (2 * STGKV)          // 208896
#define KEXP 0.12751744f               // 1/sqrt(128) * log2(e)

__global__ void __launch_bounds__(256, 1) attn_tc()
{
    extern __shared__ char smc[];
    const uint32_t sb = smem_u32(smc);
    const int tid = threadIdx.x, wid = tid >> 5, lane = tid & 31;
    const int qt   = (SS / 128 - 1) - blockIdx.x;    // longest CTAs first
    const int bh   = blockIdx.y;
    const int row0 = qt * 128;
    const size_t bbase = (size_t)bh * SS * HD;
    const int ntiles = qt + 1;

    // ---- Q fragments (fp16, single), loaded once from gmem
    uint32_t aq[8][4];
    {
        const int r0 = row0 + wid * 16 + (lane >> 2);
        const __half* p0 = g_q16 + bbase + (size_t)r0 * HD + (lane & 3) * 2;
#pragma unroll
        for (int c = 0; c < 8; c++) {
            aq[c][0] = *(const uint32_t*)(p0 + c * 16);
            aq[c][1] = *(const uint32_t*)(p0 + 8 * HD + c * 16);
            aq[c][2] = *(const uint32_t*)(p0 + c * 16 + 8);
            aq[c][3] = *(const uint32_t*)(p0 + 8 * HD + c * 16 + 8);
        }
    }

    float ctx[16][4];
#pragma unroll
    for (int i = 0; i < 16; i++)
#pragma unroll
        for (int j = 0; j < 4; j++) ctx[i][j] = 0.f;
    float mrun0 = -1e30f, mrun1 = -1e30f, lrun0 = 0.f, lrun1 = 0.f;

    auto load_kv = [&](int stage, int j0) {
        const uint32_t base = sb + stage * STGKV;
        const __half* s0 = g_k16h + bbase + (size_t)j0 * HD;
        const __half* s1 = g_k16l + bbase + (size_t)j0 * HD;
        const __half* s2 = g_v16  + bbase + (size_t)j0 * HD;
#pragma unroll
        for (int it = 0; it < 24; it++) {
            const int arr = it / 8;
            const int r   = (it & 7) * 16 + (tid >> 4);
            const int ch  = tid & 15;
            const __half* g =
                (arr == 0 ? s0 : arr == 1 ? s1 : s2) + (size_t)r * HD + ch * 8;
            CP_ASYNC16(base + arr * TILEKV + r * SROW + ch * 16, g);
        }
    };

    load_kv(0, 0);
    CP_COMMIT();

    for (int t = 0; t < ntiles; t++) {
        const int j0  = t * KT2;
        const int cur = t & 1;
        CP_WAIT0();
        __syncthreads();
        if (t + 1 < ntiles) { load_kv(cur ^ 1, (t + 1) * KT2); CP_COMMIT(); }

        const uint32_t khb = sb + cur * STGKV;
        const uint32_t klb = khb + TILEKV;
        const uint32_t vb  = khb + 2 * TILEKV;

        // ---- scores: S = Q*Kh + Q*Kl  (8 n-groups = 128 keys)
        float s[16][4];
#pragma unroll
        for (int i = 0; i < 16; i++)
#pragma unroll
            for (int j = 0; j < 4; j++) s[i][j] = 0.f;
#pragma unroll
        for (int c = 0; c < 8; c++) {
            const uint32_t koff = c * 32 + (lane >> 4) * 16;
#pragma unroll
            for (int half = 0; half < 2; half++) {
                uint32_t bkh[4][4], bkl[4][4];
#pragma unroll
                for (int g2 = 0; g2 < 4; g2++) {
                    const int ng = half * 4 + g2;
                    const uint32_t ra = (ng * 16 + (lane & 15)) * SROW + koff;
                    ldsm4(bkh[g2], khb + ra);
                    ldsm4(bkl[g2], klb + ra);
                }
#pragma unroll
                for (int prod = 0; prod < 2; prod++) {
                    const uint32_t (*bf)[4] = prod ? bkl : bkh;
#pragma unroll
                    for (int g2 = 0; g2 < 4; g2++) {
                        const int ng = half * 4 + g2;
                        mma16816h(s[2 * ng],     aq[c], bf[g2][0], bf[g2][2]);
                        mma16816h(s[2 * ng + 1], aq[c], bf[g2][1], bf[g2][3]);
                    }
                }
            }
        }

        // ---- scale (log2 domain) + causal mask (final/diagonal tile only)
#pragma unroll
        for (int nf = 0; nf < 16; nf++)
#pragma unroll
            for (int j = 0; j < 4; j++) s[nf][j] *= KEXP;
        const int qr = row0 + wid * 16 + (lane >> 2);
        if (t == ntiles - 1) {
#pragma unroll
            for (int nf = 0; nf < 16; nf++) {
                const int j = j0 + nf * 8 + (lane & 3) * 2;
                if (j     > qr)     s[nf][0] = -1e30f;
                if (j + 1 > qr)     s[nf][1] = -1e30f;
                if (j     > qr + 8) s[nf][2] = -1e30f;
                if (j + 1 > qr + 8) s[nf][3] = -1e30f;
            }
        }

        // ---- online softmax
        float mx0 = -1e30f, mx1 = -1e30f;
#pragma unroll
        for (int nf = 0; nf < 16; nf++) {
            mx0 = fmaxf(mx0, fmaxf(s[nf][0], s[nf][1]));
            mx1 = fmaxf(mx1, fmaxf(s[nf][2], s[nf][3]));
        }
        mx0 = fmaxf(mx0, __shfl_xor_sync(0xffffffff, mx0, 1));
        mx0 = fmaxf(mx0, __shfl_xor_sync(0xffffffff, mx0, 2));
        mx1 = fmaxf(mx1, __shfl_xor_sync(0xffffffff, mx1, 1));
        mx1 = fmaxf(mx1, __shfl_xor_sync(0xffffffff, mx1, 2));
        const float mn0 = fmaxf(mrun0, mx0), mn1 = fmaxf(mrun1, mx1);
        const float corr0 = ex2(mrun0 - mn0), corr1 = ex2(mrun1 - mn1);
        mrun0 = mn0; mrun1 = mn1;
        lrun0 *= corr0; lrun1 *= corr1;
#pragma unroll
        for (int nf = 0; nf < 16; nf++) {
            ctx[nf][0] *= corr0; ctx[nf][1] *= corr0;
            ctx[nf][2] *= corr1; ctx[nf][3] *= corr1;
        }

        // ---- P = exp2(s - m), pack fp16 A fragments (single)
        uint32_t ap[8][4];
        float ps0 = 0.f, ps1 = 0.f;
#pragma unroll
        for (int nf = 0; nf < 16; nf++) {
            const float p0 = ex2(s[nf][0] - mn0), p1 = ex2(s[nf][1] - mn0);
            const float p2 = ex2(s[nf][2] - mn1), p3 = ex2(s[nf][3] - mn1);
            ps0 += p0 + p1; ps1 += p2 + p3;
            const int kc = nf >> 1, hf = nf & 1;
            ap[kc][2 * hf]     = pack2h(p0, p1);
            ap[kc][2 * hf + 1] = pack2h(p2, p3);
        }
        lrun0 += ps0; lrun1 += ps1;

        // ---- ctx += P*V  (V via ldmatrix.trans, 8 k-chunks of 16 keys)
#pragma unroll
        for (int kc = 0; kc < 8; kc++) {
#pragma unroll
            for (int np = 0; np < 8; np++) {
                const uint32_t av = (kc * 16 + ((lane >> 3) & 1) * 8 + (lane & 7)) * SROW
                                  + ((lane >> 4) * 16 + np * 32);
                uint32_t bv[4];
                ldsm4t(bv, vb + av);
                mma16816h(ctx[2 * np],     ap[kc], bv[0], bv[1]);
                mma16816h(ctx[2 * np + 1], ap[kc], bv[2], bv[3]);
            }
        }
        __syncthreads();
    }

    // ---- epilogue: normalize, store fp16 ctx
    lrun0 += __shfl_xor_sync(0xffffffff, lrun0, 1);
    lrun0 += __shfl_xor_sync(0xffffffff, lrun0, 2);
    lrun1 += __shfl_xor_sync(0xffffffff, lrun1, 1);
    lrun1 += __shfl_xor_sync(0xffffffff, lrun1, 2);
    const float inv0 = 1.f / lrun0, inv1 = 1.f / lrun1;
    const int q0 = row0 + wid * 16 + (lane >> 2);
    const int b = bh >> 4, h = bh & 15;
#pragma unroll
    for (int nf = 0; nf < 16; nf++) {
        const int d = nf * 8 + (lane & 3) * 2;
        const size_t o0 = (size_t)(b * SS + q0) * DD + h * HD + d;
        const size_t o1 = o0 + (size_t)8 * DD;
        *(uint32_t*)(g_cth + o0) = pack2h(ctx[nf][0] * inv0, ctx[nf][1] * inv0);
        *(uint32_t*)(g_cth + o1) = pack2h(ctx[nf][2] * inv1, ctx[nf][3] * inv1);
    }
}

// ---------------------------------------------------------------------------
// Launch
// ---------------------------------------------------------------------------
extern "C" void kernel_launch(void* const* d_in, const int* in_sizes, int n_in,
                              void* d_out, int out_size)
{
    (void)in_sizes; (void)n_in; (void)out_size;
    const float* x  = (const float*)d_in[0];
    const float* Wq = (const float*)d_in[1];
    const float* Wk = (const float*)d_in[2];
    const float* Wv = (const float*)d_in[3];
    const float* Wo = (const float*)d_in[4];
    const float* bo = (const float*)d_in[5];
    float* out = (float*)d_out;

    cudaFuncSetAttribute(gemm_tc, cudaFuncAttributeMaxDynamicSharedMemorySize, GEMM_SMEM);
    cudaFuncSetAttribute(attn_tc, cudaFuncAttributeMaxDynamicSharedMemorySize, ATTN_SMEM);

    __half *xh_p, *cth_p;
    cudaGetSymbolAddress((void**)&xh_p, g_xh);
    cudaGetSymbolAddress((void**)&cth_p, g_cth);

    // 1. weight transpose + fp16 hi/lo split
    wtrans_split<<<dim3(DD/32, DD/32, 4), dim3(32, 8)>>>(Wq, Wk, Wv, Wo);
    // 2. round x to fp16
    round_fp16<<<(int)((size_t)MM*DD/4/256), 256>>>(x, xh_p);
    // 3. QKV projections: K = 2-product (exact W), Q/V = 1-product
    gemm_tc<<<dim3(DD/128, MM/128, 3), 256, GEMM_SMEM>>>(xh_p, nullptr, nullptr, 0);
    // 4. tensor-core flash attention (fp16, KT2=128) -> fp16 ctx
    attn_tc<<<dim3(SS/128, BB*HH), 256, ATTN_SMEM>>>();
    // 5. output projection (1-product) + bias
    gemm_tc<<<dim3(DD/128, MM/128, 1), 256, GEMM_SMEM>>>(cth_p, out, bo, 1);
}

// round 15
// speedup vs baseline: 1.8187x; 1.2815x over previous
#include <cuda_runtime.h>
#include <cuda_bf16.h>
#include <cuda_fp16.h>
#include <cstdint>
#include <math.h>

// Problem constants
#define BB 2
#define SS 2048
#define DD 2048
#define HH 16
#define HD 128
#define MM (BB*SS)   // 4096

// ---------------------------------------------------------------------------
// Scratch (static device arrays)
// ---------------------------------------------------------------------------
__device__ __half g_xh[(size_t)MM*DD];                 // fp16-rounded x
__device__ __half g_cth[(size_t)MM*DD];                // fp16-rounded ctx
__device__ __half g_wh[4][(size_t)DD*DD];              // weights^T (fp16)
// Attention operands, layout [b*H+h][s][d], all fp16-rounded
__device__ __half g_q16[(size_t)BB*HH*SS*HD];
__device__ __half g_k16[(size_t)BB*HH*SS*HD];
__device__ __half g_v16[(size_t)BB*HH*SS*HD];

// ---------------------------------------------------------------------------
// PTX helpers — baseline (sm_80+) instructions only (compute_103-safe)
// ---------------------------------------------------------------------------
__device__ __forceinline__ uint32_t smem_u32(const void* p) {
    uint32_t a;
    asm("{ .reg .u64 t; cvta.to.shared.u64 t, %1; cvt.u32.u64 %0, t; }" : "=r"(a) : "l"(p));
    return a;
}
#define CP_ASYNC16(dst, src) \
    asm volatile("cp.async.cg.shared.global [%0], [%1], 16;" :: "r"(dst), "l"(src))
#define CP_COMMIT() asm volatile("cp.async.commit_group;" ::: "memory")
#define CP_WAIT0()  asm volatile("cp.async.wait_group 0;" ::: "memory")

__device__ __forceinline__ void ldsm4(uint32_t* r, uint32_t a) {
    asm volatile("ldmatrix.sync.aligned.m8n8.x4.shared.b16 {%0,%1,%2,%3}, [%4];"
        : "=r"(r[0]), "=r"(r[1]), "=r"(r[2]), "=r"(r[3]) : "r"(a));
}
__device__ __forceinline__ void ldsm4t(uint32_t* r, uint32_t a) {
    asm volatile("ldmatrix.sync.aligned.m8n8.x4.trans.shared.b16 {%0,%1,%2,%3}, [%4];"
        : "=r"(r[0]), "=r"(r[1]), "=r"(r[2]), "=r"(r[3]) : "r"(a));
}
// fp16 MMA (all tensor work)
__device__ __forceinline__ void mma16816h(float* d, const uint32_t* a,
                                          uint32_t b0, uint32_t b1) {
    asm volatile(
        "mma.sync.aligned.m16n8k16.row.col.f32.f16.f16.f32 "
        "{%0,%1,%2,%3}, {%4,%5,%6,%7}, {%8,%9}, {%0,%1,%2,%3};"
        : "+f"(d[0]), "+f"(d[1]), "+f"(d[2]), "+f"(d[3])
        : "r"(a[0]), "r"(a[1]), "r"(a[2]), "r"(a[3]), "r"(b0), "r"(b1));
}
__device__ __forceinline__ float ex2(float x) {
    float r; asm("ex2.approx.f32 %0, %1;" : "=f"(r) : "f"(x)); return r;
}
__device__ __forceinline__ uint32_t pack2h(float v0, float v1) {
    __half2 h = __floats2half2_rn(v0, v1);
    return *(uint32_t*)&h;
}

// ---------------------------------------------------------------------------
// fp32 -> fp16 round (elementwise, layout preserved)
// ---------------------------------------------------------------------------
__global__ void __launch_bounds__(256) round_fp16(const float* __restrict__ src,
                                                  __half* __restrict__ dst)
{
    size_t i = (size_t)blockIdx.x * blockDim.x + threadIdx.x;   // per float4
    float4 v = ((const float4*)src)[i];
    ((__half2*)dst)[2*i]   = __floats2half2_rn(v.x, v.y);
    ((__half2*)dst)[2*i+1] = __floats2half2_rn(v.z, v.w);
}

// ---------------------------------------------------------------------------
// Weight transpose + fp16 round: W[K,N] fp32 -> Wt[N,K] fp16
// ---------------------------------------------------------------------------
__global__ void __launch_bounds__(256) wtrans_split(const float* __restrict__ W0,
                                                    const float* __restrict__ W1,
                                                    const float* __restrict__ W2,
                                                    const float* __restrict__ W3)
{
    int z = blockIdx.z;
    const float* W = (z == 0) ? W0 : (z == 1) ? W1 : (z == 2) ? W2 : W3;
    __half* Th = g_wh[z];
    __shared__ float t[32][33];
    int tx = threadIdx.x, ty = threadIdx.y;
    int x  = blockIdx.x * 32 + tx;
    int y0 = blockIdx.y * 32;
#pragma unroll
    for (int r = 0; r < 4; r++)
        t[ty + r*8][tx] = W[(size_t)(y0 + ty + r*8) * DD + x];
    __syncthreads();
    int xo  = y0 + tx;
    int yo0 = blockIdx.x * 32;
#pragma unroll
    for (int r = 0; r < 4; r++) {
        float v = t[tx][ty + r*8];
        Th[(size_t)(yo0 + ty + r*8) * DD + xo] = __float2half_rn(v);
    }
}

// ---------------------------------------------------------------------------
// HMMA fp16 1-product GEMM: C[M,N] = A[M,K] @ Wt^T (Wt stored [N,K])
// Tile 128x128, KC=64, 2-stage cp.async, 8 warps x (32x64), 2 CTA/SM.
// mode 0: QKV proj -> fp16 head-split store. mode 1: out proj + bias (fp32).
// ---------------------------------------------------------------------------
#define KC 64
#define NCH (DD / KC)          // 32
#define ROWB 144               // smem bytes per row (128B data + 16B pad)
#define TILE_B (128 * ROWB)    // 18432
#define STAGE_B (2 * TILE_B)   // 36864 (A, Wh)
#define GEMM_SMEM (2 * STAGE_B) // 73728 -> 2 CTA/SM

__global__ void __launch_bounds__(256, 2) gemm_tc(const __half* __restrict__ A,
                                                  float* __restrict__ out1,
                                                  const float* __restrict__ bias,
                                                  int mode)
{
    extern __shared__ char smc[];
    const uint32_t sb = smem_u32(smc);
    const int tid  = threadIdx.x;
    const int wid  = tid >> 5;
    const int lane = tid & 31;
    const int z    = blockIdx.z;
    const __half* Bh = g_wh[(mode == 0) ? z : 3];
    const int row0 = blockIdx.y * 128;
    const int col0 = blockIdx.x * 128;
    const int mw   = (wid & 3) * 32;      // warp M offset in tile
    const int nw   = (wid >> 2) * 64;     // warp N offset in tile

    float acc[2][8][4];
#pragma unroll
    for (int i = 0; i < 2; i++)
#pragma unroll
        for (int j = 0; j < 8; j++)
#pragma unroll
            for (int q = 0; q < 4; q++) acc[i][j][q] = 0.f;

    // stage loader: 2 tiles x 128 rows x 8 chunks(16B) = 2048 cp.async
    auto load_stage = [&](int stage, int c) {
        const int k0 = c * KC;
        const uint32_t base = sb + stage * STAGE_B;
#pragma unroll
        for (int j = 0; j < 8; j++) {
            int i    = tid + j * 256;
            int tile = i >> 10;           // uniform per j (1024 per tile)
            int r    = (i >> 3) & 127;
            int ch   = i & 7;
            const __half* g = (tile == 0)
                ? A  + (size_t)(row0 + r) * DD + k0 + ch * 8
                : Bh + (size_t)(col0 + r) * DD + k0 + ch * 8;
            CP_ASYNC16(base + tile * TILE_B + r * ROWB + ch * 16, g);
        }
    };

    load_stage(0, 0);
    CP_COMMIT();

    for (int c = 0; c < NCH; c++) {
        CP_WAIT0();
        __syncthreads();
        if (c + 1 < NCH) load_stage((c + 1) & 1, c + 1);
        CP_COMMIT();
        const uint32_t st = sb + (c & 1) * STAGE_B;

#pragma unroll
        for (int k16 = 0; k16 < 4; k16++) {
            const uint32_t koff = k16 * 32 + (lane >> 4) * 16;
            uint32_t af[2][4];
#pragma unroll
            for (int mm = 0; mm < 2; mm++) {
                const uint32_t ra = (mw + mm * 16 + (lane & 15)) * ROWB + koff;
                ldsm4(af[mm], st + ra);
            }
#pragma unroll
            for (int half = 0; half < 2; half++) {
                uint32_t bfh[2][4];
#pragma unroll
                for (int g2 = 0; g2 < 2; g2++) {
                    const int ng = half * 2 + g2;
                    const uint32_t rb = (nw + ng * 16 + (lane & 15)) * ROWB + koff;
                    ldsm4(bfh[g2], st + TILE_B + rb);
                }
#pragma unroll
                for (int mm = 0; mm < 2; mm++)
#pragma unroll
                    for (int g2 = 0; g2 < 2; g2++) {
                        const int ng = half * 2 + g2;
                        mma16816h(acc[mm][ng * 2],     af[mm], bfh[g2][0], bfh[g2][2]);
                        mma16816h(acc[mm][ng * 2 + 1], af[mm], bfh[g2][1], bfh[g2][3]);
                    }
            }
        }
    }

    // ---- epilogue
#pragma unroll
    for (int mm = 0; mm < 2; mm++) {
        const int m0 = row0 + mw + mm * 16 + (lane >> 2);
#pragma unroll
        for (int ng = 0; ng < 4; ng++)
#pragma unroll
            for (int hf = 0; hf < 2; hf++) {
                const int n = col0 + nw + ng * 16 + hf * 8 + 2 * (lane & 3);
                const float* d = acc[mm][ng * 2 + hf];
                if (mode == 0) {
                    __half* outp = (z == 0) ? g_q16 : (z == 1) ? g_k16 : g_v16;
                    const int h = n >> 7;
#pragma unroll
                    for (int rr = 0; rr < 2; rr++) {
                        const int m = m0 + rr * 8;
                        const int b = m >> 11, s = m & 2047;
                        size_t off = ((size_t)(b * HH + h) * SS + s) * HD + (n & 127);
                        *(uint32_t*)(outp + off) = pack2h(d[rr*2], d[rr*2+1]);
                    }
                } else {
                    const float b0 = bias[n], b1 = bias[n + 1];
#pragma unroll
                    for (int rr = 0; rr < 2; rr++) {
                        const int m = m0 + rr * 8;
                        *(float2*)(out1 + (size_t)m * DD + n) =
                            make_float2(d[rr * 2] + b0, d[rr * 2 + 1] + b1);
                    }
                }
            }
    }
}

// ---------------------------------------------------------------------------
// Tensor-core flash attention (causal), fp16 single products:
//   S = Q*K [1 product], ctx = P*V [1 product]
// KT2=128 key tiles, 2 tiles (K, V) x 2 stages = 139KB smem.
// ---------------------------------------------------------------------------
#define KT2 128
#define SROW 272
#define TILEKV (KT2 * SROW)            // 34816
#define STGKV (2 * TILEKV)             // 69632 (K, V)
#define ATTN_SMEM (2 * STGKV)          // 139264
#define KEXP 0.12751744f               // 1/sqrt(128) * log2(e)

__global__ void __launch_bounds__(256, 1) attn_tc()
{
    extern __shared__ char smc[];
    const uint32_t sb = smem_u32(smc);
    const int tid = threadIdx.x, wid = tid >> 5, lane = tid & 31;
    const int qt   = (SS / 128 - 1) - blockIdx.x;    // longest CTAs first
    const int bh   = blockIdx.y;
    const int row0 = qt * 128;
    const size_t bbase = (size_t)bh * SS * HD;
    const int ntiles = qt + 1;

    // ---- Q fragments (fp16, single), loaded once from gmem
    uint32_t aq[8][4];
    {
        const int r0 = row0 + wid * 16 + (lane >> 2);
        const __half* p0 = g_q16 + bbase + (size_t)r0 * HD + (lane & 3) * 2;
#pragma unroll
        for (int c = 0; c < 8; c++) {
            aq[c][0] = *(const uint32_t*)(p0 + c * 16);
            aq[c][1] = *(const uint32_t*)(p0 + 8 * HD + c * 16);
            aq[c][2] = *(const uint32_t*)(p0 + c * 16 + 8);
            aq[c][3] = *(const uint32_t*)(p0 + 8 * HD + c * 16 + 8);
        }
    }

    float ctx[16][4];
#pragma unroll
    for (int i = 0; i < 16; i++)
#pragma unroll
        for (int j = 0; j < 4; j++) ctx[i][j] = 0.f;
    float mrun0 = -1e30f, mrun1 = -1e30f, lrun0 = 0.f, lrun1 = 0.f;

    // KV loader: 2 tiles x 128 rows x 16 chunks(16B) = 4096 cp.async / 256 thr
    auto load_kv = [&](int stage, int j0) {
        const uint32_t base = sb + stage * STGKV;
        const __half* s0 = g_k16 + bbase + (size_t)j0 * HD;
        const __half* s1 = g_v16 + bbase + (size_t)j0 * HD;
#pragma unroll
        for (int it = 0; it < 16; it++) {
            const int arr = it >> 3;
            const int r   = (it & 7) * 16 + (tid >> 4);
            const int ch  = tid & 15;
            const __half* g = (arr == 0 ? s0 : s1) + (size_t)r * HD + ch * 8;
            CP_ASYNC16(base + arr * TILEKV + r * SROW + ch * 16, g);
        }
    };

    load_kv(0, 0);
    CP_COMMIT();

    for (int t = 0; t < ntiles; t++) {
        const int j0  = t * KT2;
        const int cur = t & 1;
        CP_WAIT0();
        __syncthreads();
        if (t + 1 < ntiles) { load_kv(cur ^ 1, (t + 1) * KT2); CP_COMMIT(); }

        const uint32_t kb = sb + cur * STGKV;
        const uint32_t vb = kb + TILEKV;

        // ---- scores: S = Q*K  (8 n-groups = 128 keys)
        float s[16][4];
#pragma unroll
        for (int i = 0; i < 16; i++)
#pragma unroll
            for (int j = 0; j < 4; j++) s[i][j] = 0.f;
#pragma unroll
        for (int c = 0; c < 8; c++) {
            const uint32_t koff = c * 32 + (lane >> 4) * 16;
#pragma unroll
            for (int half = 0; half < 2; half++) {
                uint32_t bk[4][4];
#pragma unroll
                for (int g2 = 0; g2 < 4; g2++) {
                    const int ng = half * 4 + g2;
                    const uint32_t ra = (ng * 16 + (lane & 15)) * SROW + koff;
                    ldsm4(bk[g2], kb + ra);
                }
#pragma unroll
                for (int g2 = 0; g2 < 4; g2++) {
                    const int ng = half * 4 + g2;
                    mma16816h(s[2 * ng],     aq[c], bk[g2][0], bk[g2][2]);
                    mma16816h(s[2 * ng + 1], aq[c], bk[g2][1], bk[g2][3]);
                }
            }
        }

        // ---- scale (log2 domain) + causal mask (final/diagonal tile only)
#pragma unroll
        for (int nf = 0; nf < 16; nf++)
#pragma unroll
            for (int j = 0; j < 4; j++) s[nf][j] *= KEXP;
        const int qr = row0 + wid * 16 + (lane >> 2);
        if (t == ntiles - 1) {
#pragma unroll
            for (int nf = 0; nf < 16; nf++) {
                const int j = j0 + nf * 8 + (lane & 3) * 2;
                if (j     > qr)     s[nf][0] = -1e30f;
                if (j + 1 > qr)     s[nf][1] = -1e30f;
                if (j     > qr + 8) s[nf][2] = -1e30f;
                if (j + 1 > qr + 8) s[nf][3] = -1e30f;
            }
        }

        // ---- online softmax
        float mx0 = -1e30f, mx1 = -1e30f;
#pragma unroll
        for (int nf = 0; nf < 16; nf++) {
            mx0 = fmaxf(mx0, fmaxf(s[nf][0], s[nf][1]));
            mx1 = fmaxf(mx1, fmaxf(s[nf][2], s[nf][3]));
        }
        mx0 = fmaxf(mx0, __shfl_xor_sync(0xffffffff, mx0, 1));
        mx0 = fmaxf(mx0, __shfl_xor_sync(0xffffffff, mx0, 2));
        mx1 = fmaxf(mx1, __shfl_xor_sync(0xffffffff, mx1, 1));
        mx1 = fmaxf(mx1, __shfl_xor_sync(0xffffffff, mx1, 2));
        const float mn0 = fmaxf(mrun0, mx0), mn1 = fmaxf(mrun1, mx1);
        const float corr0 = ex2(mrun0 - mn0), corr1 = ex2(mrun1 - mn1);
        mrun0 = mn0; mrun1 = mn1;
        lrun0 *= corr0; lrun1 *= corr1;
#pragma unroll
        for (int nf = 0; nf < 16; nf++) {
            ctx[nf][0] *= corr0; ctx[nf][1] *= corr0;
            ctx[nf][2] *= corr1; ctx[nf][3] *= corr1;
        }

        // ---- P = exp2(s - m), pack fp16 A fragments (single)
        uint32_t ap[8][4];
        float ps0 = 0.f, ps1 = 0.f;
#pragma unroll
        for (int nf = 0; nf < 16; nf++) {
            const float p0 = ex2(s[nf][0] - mn0), p1 = ex2(s[nf][1] - mn0);
            const float p2 = ex2(s[nf][2] - mn1), p3 = ex2(s[nf][3] - mn1);
            ps0 += p0 + p1; ps1 += p2 + p3;
            const int kc = nf >> 1, hf = nf & 1;
            ap[kc][2 * hf]     = pack2h(p0, p1);
            ap[kc][2 * hf + 1] = pack2h(p2, p3);
        }
        lrun0 += ps0; lrun1 += ps1;

        // ---- ctx += P*V  (V via ldmatrix.trans, 8 k-chunks of 16 keys)
#pragma unroll
        for (int kc = 0; kc < 8; kc++) {
#pragma unroll
            for (int np = 0; np < 8; np++) {
                const uint32_t av = (kc * 16 + ((lane >> 3) & 1) * 8 + (lane & 7)) * SROW
                                  + ((lane >> 4) * 16 + np * 32);
                uint32_t bv[4];
                ldsm4t(bv, vb + av);
                mma16816h(ctx[2 * np],     ap[kc], bv[0], bv[1]);
                mma16816h(ctx[2 * np + 1], ap[kc], bv[2], bv[3]);
            }
        }
        __syncthreads();
    }

    // ---- epilogue: normalize, store fp16 ctx
    lrun0 += __shfl_xor_sync(0xffffffff, lrun0, 1);
    lrun0 += __shfl_xor_sync(0xffffffff, lrun0, 2);
    lrun1 += __shfl_xor_sync(0xffffffff, lrun1, 1);
    lrun1 += __shfl_xor_sync(0xffffffff, lrun1, 2);
    const float inv0 = 1.f / lrun0, inv1 = 1.f / lrun1;
    const int q0 = row0 + wid * 16 + (lane >> 2);
    const int b = bh >> 4, h = bh & 15;
#pragma unroll
    for (int nf = 0; nf < 16; nf++) {
        const int d = nf * 8 + (lane & 3) * 2;
        const size_t o0 = (size_t)(b * SS + q0) * DD + h * HD + d;
        const size_t o1 = o0 + (size_t)8 * DD;
        *(uint32_t*)(g_cth + o0) = pack2h(ctx[nf][0] * inv0, ctx[nf][1] * inv0);
        *(uint32_t*)(g_cth + o1) = pack2h(ctx[nf][2] * inv1, ctx[nf][3] * inv1);
    }
}

// ---------------------------------------------------------------------------
// Launch
// ---------------------------------------------------------------------------
extern "C" void kernel_launch(void* const* d_in, const int* in_sizes, int n_in,
                              void* d_out, int out_size)
{
    (void)in_sizes; (void)n_in; (void)out_size;
    const float* x  = (const float*)d_in[0];
    const float* Wq = (const float*)d_in[1];
    const float* Wk = (const float*)d_in[2];
    const float* Wv = (const float*)d_in[3];
    const float* Wo = (const float*)d_in[4];
    const float* bo = (const float*)d_in[5];
    float* out = (float*)d_out;

    cudaFuncSetAttribute(gemm_tc, cudaFuncAttributeMaxDynamicSharedMemorySize, GEMM_SMEM);
    cudaFuncSetAttribute(attn_tc, cudaFuncAttributeMaxDynamicSharedMemorySize, ATTN_SMEM);

    __half *xh_p, *cth_p;
    cudaGetSymbolAddress((void**)&xh_p, g_xh);
    cudaGetSymbolAddress((void**)&cth_p, g_cth);

    // 1. weight transpose + fp16 round
    wtrans_split<<<dim3(DD/32, DD/32, 4), dim3(32, 8)>>>(Wq, Wk, Wv, Wo);
    // 2. round x to fp16
    round_fp16<<<(int)((size_t)MM*DD/4/256), 256>>>(x, xh_p);
    // 3. QKV projections (fp16 1-product) -> Q / K / V fp16
    gemm_tc<<<dim3(DD/128, MM/128, 3), 256, GEMM_SMEM>>>(xh_p, nullptr, nullptr, 0);
    // 4. tensor-core flash attention (fp16, 1+1 products) -> fp16 ctx
    attn_tc<<<dim3(SS/128, BB*HH), 256, ATTN_SMEM>>>();
    // 5. output projection (1-product) + bias
    gemm_tc<<<dim3(DD/128, MM/128, 1), 256, GEMM_SMEM>>>(cth_p, out, bo, 1);
}